// round 2
// baseline (speedup 1.0000x reference)
#include <cuda_runtime.h>
#include <math.h>
#include <stdint.h>

// Problem dims
#define Bsz   32
#define Ssz   1024
#define Dsz   512
#define Hh    16
#define NBlk  12
#define DHd   32
#define FFd   2048
#define MROWS (Bsz*Ssz)            // 32768
#define QKVW  96                   // 3*DHd

// ---------------- scratch (allocation-free: __device__ globals) ----------------
__device__ float g_x  [(size_t)Bsz*Ssz*Dsz];   // 64MB  current activations
__device__ float g_y  [(size_t)Bsz*Ssz*Dsz];   // 64MB  pre-LN temp
__device__ float g_xh [(size_t)Bsz*Ssz*Dsz];   // 64MB  concat of head outputs
__device__ float g_qkv[(size_t)Bsz*Ssz*QKVW];  // 12MB  per-head q|k|v
__device__ float g_h1 [(size_t)Bsz*Ssz*FFd];   // 256MB ffn hidden

// ---------------- embedding + positional encoding ----------------
__global__ void embed_kernel(const int* __restrict__ tok,
                             const float* __restrict__ emb,
                             float* __restrict__ x)
{
    int64_t i = (int64_t)blockIdx.x * blockDim.x + threadIdx.x;
    if (i >= (int64_t)Bsz * Ssz * Dsz) return;
    int d      = (int)(i & (Dsz - 1));
    int64_t bs = i >> 9;                 // / Dsz
    int s      = (int)(bs & (Ssz - 1));
    int t      = tok[bs];
    int j      = d >> 1;
    float e    = (2.0f * (float)j) / (float)Dsz;
    float freq = expf(-e * 9.210340371976184f);   // ln(10000)
    float ang  = (float)s * freq;
    float p    = (d & 1) ? cosf(ang) : sinf(ang);
    x[i] = emb[(int64_t)t * Dsz + d] + p;
}

// ---------------- generic SGEMM: C[M,N] = A[M,K](lda) @ W[K,N] + bias (+relu / +resid) ----------------
#define BM 128
#define BN 128
#define BKk 16
#define TM 8
#define TN 8

// EPI: 0 = bias, 1 = bias+relu, 2 = bias+resid
template<int EPI>
__global__ __launch_bounds__(256)
void sgemm_kernel(const float* __restrict__ A, int lda,
                  const float* __restrict__ W, int N_,
                  const float* __restrict__ bias,
                  const float* __restrict__ resid, int ldr,
                  float* __restrict__ C, int ldc,
                  int K)
{
    __shared__ float As[BKk][BM];
    __shared__ float Bs[BKk][BN];
    const int tid  = threadIdx.x;
    const int row0 = blockIdx.y * BM;
    const int col0 = blockIdx.x * BN;
    const int tr   = (tid >> 4) * TM;
    const int tc   = (tid & 15) * TN;

    float acc[TM][TN];
    #pragma unroll
    for (int i = 0; i < TM; ++i)
        #pragma unroll
        for (int j = 0; j < TN; ++j) acc[i][j] = 0.f;

    for (int k0 = 0; k0 < K; k0 += BKk) {
        // A tile: 128 rows x 16 k, float4 along k
        #pragma unroll
        for (int i = 0; i < 2; ++i) {
            int idx = tid + i * 256;            // 0..511 float4s
            int r   = idx >> 2;
            int c   = (idx & 3) << 2;
            const float4 v = *(const float4*)(A + (size_t)(row0 + r) * lda + k0 + c);
            As[c + 0][r] = v.x; As[c + 1][r] = v.y; As[c + 2][r] = v.z; As[c + 3][r] = v.w;
        }
        // B tile: 16 k x 128 cols, float4 along n (zero-fill past N_)
        #pragma unroll
        for (int i = 0; i < 2; ++i) {
            int idx = tid + i * 256;            // 0..511 float4s
            int r   = idx >> 5;
            int c   = (idx & 31) << 2;
            int gc  = col0 + c;
            float4 v = make_float4(0.f, 0.f, 0.f, 0.f);
            if (gc < N_) v = *(const float4*)(W + (size_t)(k0 + r) * N_ + gc);
            Bs[r][c + 0] = v.x; Bs[r][c + 1] = v.y; Bs[r][c + 2] = v.z; Bs[r][c + 3] = v.w;
        }
        __syncthreads();
        #pragma unroll
        for (int kk = 0; kk < BKk; ++kk) {
            float a[TM], bb[TN];
            #pragma unroll
            for (int i = 0; i < TM; ++i) a[i] = As[kk][tr + i];
            #pragma unroll
            for (int j = 0; j < TN; ++j) bb[j] = Bs[kk][tc + j];
            #pragma unroll
            for (int i = 0; i < TM; ++i)
                #pragma unroll
                for (int j = 0; j < TN; ++j) acc[i][j] += a[i] * bb[j];
        }
        __syncthreads();
    }

    #pragma unroll
    for (int i = 0; i < TM; ++i) {
        int row = row0 + tr + i;
        #pragma unroll
        for (int j = 0; j < TN; ++j) {
            int col = col0 + tc + j;
            if (col < N_) {
                float v = acc[i][j] + bias[col];
                if (EPI == 1) v = fmaxf(v, 0.f);
                if (EPI == 2) v += resid[(size_t)row * ldr + col];
                C[(size_t)row * ldc + col] = v;
            }
        }
    }
}

// ---------------- fused attention for one head-step ----------------
// qkv: [B, S, 96] (q|k|v).  out slice: xh + h*32, row stride Dsz.
// scores are tiny (|s| << 88) -> single-pass exp without running max.
#define QT 128
#define KT 32
#define ATTN_SCALE 0.03125f   // 1/sqrt(1024)

__global__ __launch_bounds__(128)
void attn_kernel(const float* __restrict__ qkv, float* __restrict__ outp)
{
    __shared__ float Ks[KT][DHd];
    __shared__ float Vs[KT][DHd];
    const int b = blockIdx.y;
    const int t = threadIdx.x;
    const int qrow = blockIdx.x * QT + t;
    const float* base = qkv + (size_t)b * Ssz * QKVW;

    float q[DHd];
    #pragma unroll
    for (int i = 0; i < 8; ++i) {
        float4 v = *(const float4*)(base + (size_t)qrow * QKVW + i * 4);
        q[i*4+0] = v.x; q[i*4+1] = v.y; q[i*4+2] = v.z; q[i*4+3] = v.w;
    }
    float o[DHd];
    #pragma unroll
    for (int d = 0; d < DHd; ++d) o[d] = 0.f;
    float l = 0.f;

    for (int k0 = 0; k0 < Ssz; k0 += KT) {
        // cooperative load of K/V chunk: KT*32 floats each = 256 float4 each
        #pragma unroll
        for (int i = 0; i < 2; ++i) {
            int idx = t + i * 128;            // 0..255
            int r   = idx >> 3;               // key row in chunk
            int c   = (idx & 7) << 2;         // dim
            const float* src = base + (size_t)(k0 + r) * QKVW;
            float4 kv = *(const float4*)(src + 32 + c);
            Ks[r][c+0] = kv.x; Ks[r][c+1] = kv.y; Ks[r][c+2] = kv.z; Ks[r][c+3] = kv.w;
            float4 vv = *(const float4*)(src + 64 + c);
            Vs[r][c+0] = vv.x; Vs[r][c+1] = vv.y; Vs[r][c+2] = vv.z; Vs[r][c+3] = vv.w;
        }
        __syncthreads();
        #pragma unroll 8
        for (int j = 0; j < KT; ++j) {
            float s = 0.f;
            #pragma unroll
            for (int d = 0; d < DHd; ++d) s += q[d] * Ks[j][d];
            float p = __expf(s * ATTN_SCALE);
            l += p;
            #pragma unroll
            for (int d = 0; d < DHd; ++d) o[d] += p * Vs[j][d];
        }
        __syncthreads();
    }

    const float inv = 1.f / l;
    float* dst = outp + ((size_t)b * Ssz + qrow) * Dsz;
    #pragma unroll
    for (int i = 0; i < 8; ++i) {
        float4 v = make_float4(o[i*4]*inv, o[i*4+1]*inv, o[i*4+2]*inv, o[i*4+3]*inv);
        *(float4*)(dst + i * 4) = v;
    }
}

// ---------------- LayerNorm over last dim (512), eps=1e-3 ----------------
__global__ __launch_bounds__(128)
void ln_kernel(const float* __restrict__ y, const float* __restrict__ g,
               const float* __restrict__ be, float* __restrict__ x)
{
    const int row = blockIdx.x;
    const int t = threadIdx.x;
    const float* yr = y + (size_t)row * Dsz;
    float4 v = *(const float4*)(yr + t * 4);
    float sum = v.x + v.y + v.z + v.w;
    float sq  = v.x*v.x + v.y*v.y + v.z*v.z + v.w*v.w;
    #pragma unroll
    for (int o = 16; o > 0; o >>= 1) {
        sum += __shfl_down_sync(0xffffffffu, sum, o);
        sq  += __shfl_down_sync(0xffffffffu, sq,  o);
    }
    __shared__ float ws[4], ws2[4];
    int warp = t >> 5, lane = t & 31;
    if (lane == 0) { ws[warp] = sum; ws2[warp] = sq; }
    __syncthreads();
    if (t == 0) {
        ws[0]  = ws[0] + ws[1] + ws[2] + ws[3];
        ws2[0] = ws2[0] + ws2[1] + ws2[2] + ws2[3];
    }
    __syncthreads();
    const float mean = ws[0] * (1.f / (float)Dsz);
    const float var  = ws2[0] * (1.f / (float)Dsz) - mean * mean;
    const float r    = rsqrtf(var + 1e-3f);
    float4 gg = *(const float4*)(g + t * 4);
    float4 bb = *(const float4*)(be + t * 4);
    float4 out;
    out.x = (v.x - mean) * r * gg.x + bb.x;
    out.y = (v.y - mean) * r * gg.y + bb.y;
    out.z = (v.z - mean) * r * gg.z + bb.z;
    out.w = (v.w - mean) * r * gg.w + bb.w;
    *(float4*)(x + (size_t)row * Dsz + t * 4) = out;
}

// ---------------- mean-pool + final dense + sigmoid ----------------
__global__ __launch_bounds__(256)
void final_kernel(const float* __restrict__ x, const float* __restrict__ Wf,
                  const float* __restrict__ bf, float* __restrict__ out, int out_size)
{
    const int b = blockIdx.x;
    const float* xb = x + (size_t)b * Ssz * Dsz;
    float acc = 0.f;
    for (int i = threadIdx.x; i < (Ssz * Dsz) / 4; i += 256) {
        float4 v = *(const float4*)(xb + (size_t)i * 4);
        int d = (i * 4) & (Dsz - 1);
        acc += v.x * Wf[d] + v.y * Wf[d+1] + v.z * Wf[d+2] + v.w * Wf[d+3];
    }
    #pragma unroll
    for (int o = 16; o > 0; o >>= 1) acc += __shfl_down_sync(0xffffffffu, acc, o);
    __shared__ float ws[8];
    int warp = threadIdx.x >> 5, lane = threadIdx.x & 31;
    if (lane == 0) ws[warp] = acc;
    __syncthreads();
    if (threadIdx.x == 0) {
        float tot = 0.f;
        #pragma unroll
        for (int w = 0; w < 8; ++w) tot += ws[w];
        float logit = tot * (1.f / (float)Ssz) + bf[0];
        if (b < out_size) out[b] = logit;
        if (Bsz + b < out_size) out[Bsz + b] = 1.f / (1.f + expf(-logit));
    }
}

// ---------------- orchestration ----------------
extern "C" void kernel_launch(void* const* d_in, const int* in_sizes, int n_in,
                              void* d_out, int out_size)
{
    const int*   tok = (const int*)  d_in[0];
    const float* emb = (const float*)d_in[1];
    const float* W0  = (const float*)d_in[2];
    const float* b0  = (const float*)d_in[3];
    const float* Wh  = (const float*)d_in[4];
    const float* bh  = (const float*)d_in[5];
    const float* Wo  = (const float*)d_in[6];
    const float* bo  = (const float*)d_in[7];
    const float* g1  = (const float*)d_in[8];
    const float* be1 = (const float*)d_in[9];
    const float* W1  = (const float*)d_in[10];
    const float* b1  = (const float*)d_in[11];
    const float* W2  = (const float*)d_in[12];
    const float* b2  = (const float*)d_in[13];
    const float* g2  = (const float*)d_in[14];
    const float* be2 = (const float*)d_in[15];
    const float* Wf  = (const float*)d_in[16];
    const float* bf  = (const float*)d_in[17];
    float* out = (float*)d_out;

    float *x, *y, *xh, *qkv, *h1;
    cudaGetSymbolAddress((void**)&x,   g_x);
    cudaGetSymbolAddress((void**)&y,   g_y);
    cudaGetSymbolAddress((void**)&xh,  g_xh);
    cudaGetSymbolAddress((void**)&qkv, g_qkv);
    cudaGetSymbolAddress((void**)&h1,  g_h1);

    {
        int64_t tot = (int64_t)Bsz * Ssz * Dsz;
        embed_kernel<<<(unsigned)((tot + 255) / 256), 256>>>(tok, emb, x);
    }

    const dim3 gemm_proj(1, MROWS / BM);     // N=96
    const dim3 gemm_d(Dsz / BN, MROWS / BM); // N=512
    const dim3 gemm_f(FFd / BN, MROWS / BM); // N=2048
    const dim3 attn_grid(Ssz / QT, Bsz);

    for (int l = 0; l < NBlk; ++l) {
        // head 0: D -> 96
        sgemm_kernel<0><<<gemm_proj, 256>>>(x, Dsz,
            W0 + (size_t)l * Dsz * QKVW, QKVW, b0 + (size_t)l * QKVW,
            nullptr, 0, qkv, QKVW, Dsz);
        attn_kernel<<<attn_grid, 128>>>(qkv, xh + 0);

        // chained heads 1..15: DH -> 96
        for (int h = 1; h < Hh; ++h) {
            const float* Whl = Wh + ((size_t)l * (Hh - 1) + (h - 1)) * DHd * QKVW;
            const float* bhl = bh + ((size_t)l * (Hh - 1) + (h - 1)) * QKVW;
            sgemm_kernel<0><<<gemm_proj, 256>>>(xh + (size_t)(h - 1) * DHd, Dsz,
                Whl, QKVW, bhl, nullptr, 0, qkv, QKVW, DHd);
            attn_kernel<<<attn_grid, 128>>>(qkv, xh + (size_t)h * DHd);
        }

        // output projection + residual, then LN1
        sgemm_kernel<2><<<gemm_d, 256>>>(xh, Dsz,
            Wo + (size_t)l * Dsz * Dsz, Dsz, bo + (size_t)l * Dsz,
            x, Dsz, y, Dsz, Dsz);
        ln_kernel<<<MROWS, 128>>>(y, g1 + (size_t)l * Dsz, be1 + (size_t)l * Dsz, x);

        // FFN
        sgemm_kernel<1><<<gemm_f, 256>>>(x, Dsz,
            W1 + (size_t)l * Dsz * FFd, FFd, b1 + (size_t)l * FFd,
            nullptr, 0, h1, FFd, Dsz);
        sgemm_kernel<2><<<gemm_d, 256>>>(h1, FFd,
            W2 + (size_t)l * FFd * Dsz, Dsz, b2 + (size_t)l * Dsz,
            x, Dsz, y, Dsz, FFd);
        ln_kernel<<<MROWS, 128>>>(y, g2 + (size_t)l * Dsz, be2 + (size_t)l * Dsz, x);
    }

    final_kernel<<<Bsz, 256>>>(x, Wf, bf, out, out_size);
}

// round 4
// speedup vs baseline: 1.6425x; 1.6425x over previous
#include <cuda_runtime.h>
#include <cuda_bf16.h>
#include <math.h>
#include <stdint.h>

// Problem dims
#define Bsz   32
#define Ssz   1024
#define Dsz   512
#define Hh    16
#define NBlk  12
#define DHd   32
#define FFd   2048
#define MROWS (Bsz*Ssz)            // 32768
#define QKVW  96                   // 3*DHd

typedef __nv_bfloat16 bf16;

// ---------------- scratch (allocation-free: __device__ globals) ----------------
__device__ float g_x  [(size_t)MROWS*Dsz];    // current activations (fp32)
__device__ float g_y  [(size_t)MROWS*Dsz];    // pre-LN temp
__device__ float g_xh [(size_t)MROWS*Dsz];    // concat of head outputs (fp32)
__device__ float g_qkv[(size_t)MROWS*QKVW];   // per-head q|k|v
__device__ bf16  g_xhh[(size_t)MROWS*Dsz];    // xh bf16 hi
__device__ bf16  g_xhl[(size_t)MROWS*Dsz];    // xh bf16 lo
__device__ bf16  g_xbh[(size_t)MROWS*Dsz];    // x (post-LN1) bf16 hi
__device__ bf16  g_xbl[(size_t)MROWS*Dsz];    // x (post-LN1) bf16 lo
__device__ bf16  g_h1h[(size_t)MROWS*FFd];    // ffn hidden bf16 hi
__device__ bf16  g_h1l[(size_t)MROWS*FFd];    // ffn hidden bf16 lo
__device__ bf16  g_woth[(size_t)NBlk*Dsz*Dsz];   // Wo^T bf16 hi   [N=512,K=512]
__device__ bf16  g_wotl[(size_t)NBlk*Dsz*Dsz];
__device__ bf16  g_w1th[(size_t)NBlk*FFd*Dsz];   // W1^T           [N=2048,K=512]
__device__ bf16  g_w1tl[(size_t)NBlk*FFd*Dsz];
__device__ bf16  g_w2th[(size_t)NBlk*Dsz*FFd];   // W2^T           [N=512,K=2048]
__device__ bf16  g_w2tl[(size_t)NBlk*Dsz*FFd];

// ================= low-level helpers =================
__device__ __forceinline__ uint32_t smem_u32(const void* p) {
    uint32_t a;
    asm("{ .reg .u64 t; cvta.to.shared.u64 t, %1; cvt.u32.u64 %0, t; }" : "=r"(a) : "l"(p));
    return a;
}
static __device__ __forceinline__ uint32_t swz128(uint32_t off) { return off ^ ((off >> 3) & 0x70u); }

__device__ __forceinline__ void cp16(uint32_t smem, const void* gmem) {
    asm volatile("cp.async.cg.shared.global [%0], [%1], 16;" :: "r"(smem), "l"(gmem));
}
__device__ __forceinline__ void cp_commit() { asm volatile("cp.async.commit_group;"); }
__device__ __forceinline__ void cp_wait0() { asm volatile("cp.async.wait_group 0;"); }
__device__ __forceinline__ void cp_wait1() { asm volatile("cp.async.wait_group 1;"); }

__device__ __forceinline__ void ldm_x4(uint32_t addr, uint32_t& r0, uint32_t& r1, uint32_t& r2, uint32_t& r3) {
    asm volatile("ldmatrix.sync.aligned.m8n8.x4.shared.b16 {%0,%1,%2,%3}, [%4];"
                 : "=r"(r0), "=r"(r1), "=r"(r2), "=r"(r3) : "r"(addr));
}
__device__ __forceinline__ void mma16816(float* c, uint32_t a0, uint32_t a1, uint32_t a2, uint32_t a3,
                                         uint32_t b0, uint32_t b1) {
    asm volatile("mma.sync.aligned.m16n8k16.row.col.f32.bf16.bf16.f32 "
                 "{%0,%1,%2,%3}, {%4,%5,%6,%7}, {%8,%9}, {%0,%1,%2,%3};"
                 : "+f"(c[0]), "+f"(c[1]), "+f"(c[2]), "+f"(c[3])
                 : "r"(a0), "r"(a1), "r"(a2), "r"(a3), "r"(b0), "r"(b1));
}

// ================= embedding + positional encoding =================
__global__ void embed_kernel(const int* __restrict__ tok,
                             const float* __restrict__ emb,
                             float* __restrict__ x)
{
    int64_t i = (int64_t)blockIdx.x * blockDim.x + threadIdx.x;
    if (i >= (int64_t)Bsz * Ssz * Dsz) return;
    int d      = (int)(i & (Dsz - 1));
    int64_t bs = i >> 9;
    int s      = (int)(bs & (Ssz - 1));
    int t      = tok[bs];
    int j      = d >> 1;
    float e    = (2.0f * (float)j) / (float)Dsz;
    float freq = expf(-e * 9.210340371976184f);
    float ang  = (float)s * freq;
    float p    = (d & 1) ? cosf(ang) : sinf(ang);
    x[i] = emb[(int64_t)t * Dsz + d] + p;
}

// ================= weight transpose + bf16 split =================
// W [K,N] fp32 -> Th/Tl [N,K] bf16 (per layer z)
__global__ __launch_bounds__(256)
void wsplit_kernel(const float* __restrict__ W, bf16* __restrict__ Th, bf16* __restrict__ Tl,
                   int K, int N)
{
    __shared__ float t[32][33];
    int z = blockIdx.z;
    const float* Wz = W + (size_t)z * K * N;
    bf16* Thz = Th + (size_t)z * K * N;
    bf16* Tlz = Tl + (size_t)z * K * N;
    int n0 = blockIdx.x * 32, k0 = blockIdx.y * 32;
    int tx = threadIdx.x & 31, ty = threadIdx.x >> 5;   // 32 x 8
    #pragma unroll
    for (int i = 0; i < 4; ++i)
        t[ty + i*8][tx] = Wz[(size_t)(k0 + ty + i*8) * N + n0 + tx];
    __syncthreads();
    #pragma unroll
    for (int i = 0; i < 4; ++i) {
        float v = t[tx][ty + i*8];
        bf16 h = __float2bfloat16(v);
        bf16 lo = __float2bfloat16(v - __bfloat162float(h));
        size_t o = (size_t)(n0 + ty + i*8) * K + k0 + tx;
        Thz[o] = h; Tlz[o] = lo;
    }
}

// ================= mma.sync bf16-split GEMM =================
// C[M,N] = A[M,K] @ Bt[N,K]^T ; A/Bt as bf16 hi/lo pairs; fp32 accumulate.
// CTA 128x128, BK=64, 2-stage cp.async pipeline, 8 warps (2 M x 4 N), warp tile 64x32.
// EPI 0: out fp32 = acc + bias + resid
// EPI 1: out bf16 hi/lo = split(relu(acc + bias))
#define GBM 128
#define GBN 128
#define GBK 64
#define ST_AH 0
#define ST_AL 16384
#define ST_BH 32768
#define ST_BL 49152
#define STAGE_BYTES 65536
#define GDYN (2*STAGE_BYTES)

template<int EPI>
__global__ __launch_bounds__(256, 1)
void gemm_mma(const bf16* __restrict__ Ah, const bf16* __restrict__ Al,
              const bf16* __restrict__ Bh, const bf16* __restrict__ Bl,
              const float* __restrict__ bias,
              const float* __restrict__ resid,
              float* __restrict__ Cf,
              bf16* __restrict__ Chh, bf16* __restrict__ Chl,
              int K, int Nld)
{
    extern __shared__ char dsm[];
    const uint32_t sb = smem_u32(dsm);

    const int tid  = threadIdx.x;
    const int lane = tid & 31;
    const int w    = tid >> 5;           // 8 warps
    const int wm   = w >> 2;             // 0..1  (64-row slice)
    const int wn   = w & 3;              // 0..3  (32-col slice)
    const int row0 = blockIdx.y * GBM;
    const int col0 = blockIdx.x * GBN;

    // per-thread load indices (16B granules)
    const int lr = tid >> 3;             // 0..31 base row
    const int lc = tid & 7;              // 16B column within 128B row
    const uint32_t lso = swz128((uint32_t)(lr * 128 + lc * 16));
    const size_t  lgo = (size_t)lr * K + lc * 8;

    float acc[4][4][4];
    #pragma unroll
    for (int i = 0; i < 4; ++i)
        #pragma unroll
        for (int j = 0; j < 4; ++j)
            #pragma unroll
            for (int k = 0; k < 4; ++k) acc[i][j][k] = 0.f;

    const int nchunks = K / GBK;

    // ---- load one stage ----
    auto load_stage = [&](int c, int st) {
        const uint32_t s0 = sb + st * STAGE_BYTES;
        const size_t kofs = (size_t)c * GBK;
        const size_t ga = (size_t)row0 * K + kofs + lgo;
        const size_t gb = (size_t)col0 * K + kofs + lgo;
        #pragma unroll
        for (int i = 0; i < 4; ++i) {
            uint32_t so = swz128((uint32_t)((lr + i*32) * 128 + lc * 16));
            size_t   go = (size_t)(i*32) * K;
            cp16(s0 + ST_AH + so, Ah + ga + go);
            cp16(s0 + ST_AL + so, Al + ga + go);
            cp16(s0 + ST_BH + so, Bh + gb + go);
            cp16(s0 + ST_BL + so, Bl + gb + go);
        }
        cp_commit();
    };

    load_stage(0, 0);

    for (int c = 0; c < nchunks; ++c) {
        const int st = c & 1;
        if (c + 1 < nchunks) { load_stage(c + 1, st ^ 1); cp_wait1(); }
        else                 { cp_wait0(); }
        __syncthreads();

        const uint32_t s0 = sb + st * STAGE_BYTES;
        // A frag addr pieces
        const int arow = wm * 64 + (lane & 15);
        const int acolb = (lane >> 4) << 4;                 // 0 or 16 bytes
        const int nrow = wn * 32 + ((lane >> 4) << 3) + (lane & 7);
        const int bcolb = ((lane >> 3) & 1) << 4;           // 0 or 16 bytes

        #pragma unroll
        for (int slab = 0; slab < 4; ++slab) {
            const int kb = slab * 32;                       // byte offset of k16 slab
            uint32_t ah[4][4], al[4][4], bh[2][4], bl[2][4];
            #pragma unroll
            for (int mf = 0; mf < 4; ++mf) {
                uint32_t ao = swz128((uint32_t)((arow + mf*16) * 128 + kb + acolb));
                ldm_x4(s0 + ST_AH + ao, ah[mf][0], ah[mf][1], ah[mf][2], ah[mf][3]);
                ldm_x4(s0 + ST_AL + ao, al[mf][0], al[mf][1], al[mf][2], al[mf][3]);
            }
            #pragma unroll
            for (int ng = 0; ng < 2; ++ng) {
                uint32_t bo = swz128((uint32_t)((nrow + ng*16) * 128 + kb + bcolb));
                ldm_x4(s0 + ST_BH + bo, bh[ng][0], bh[ng][1], bh[ng][2], bh[ng][3]);
                ldm_x4(s0 + ST_BL + bo, bl[ng][0], bl[ng][1], bl[ng][2], bl[ng][3]);
            }
            #pragma unroll
            for (int mf = 0; mf < 4; ++mf) {
                #pragma unroll
                for (int ng = 0; ng < 2; ++ng) {
                    // Ahi*Bhi
                    mma16816(acc[mf][2*ng],   ah[mf][0], ah[mf][1], ah[mf][2], ah[mf][3], bh[ng][0], bh[ng][1]);
                    mma16816(acc[mf][2*ng+1], ah[mf][0], ah[mf][1], ah[mf][2], ah[mf][3], bh[ng][2], bh[ng][3]);
                    // Ahi*Blo
                    mma16816(acc[mf][2*ng],   ah[mf][0], ah[mf][1], ah[mf][2], ah[mf][3], bl[ng][0], bl[ng][1]);
                    mma16816(acc[mf][2*ng+1], ah[mf][0], ah[mf][1], ah[mf][2], ah[mf][3], bl[ng][2], bl[ng][3]);
                    // Alo*Bhi
                    mma16816(acc[mf][2*ng],   al[mf][0], al[mf][1], al[mf][2], al[mf][3], bh[ng][0], bh[ng][1]);
                    mma16816(acc[mf][2*ng+1], al[mf][0], al[mf][1], al[mf][2], al[mf][3], bh[ng][2], bh[ng][3]);
                }
            }
        }
        __syncthreads();
    }

    // ---------- epilogue ----------
    const int rg = lane >> 2;            // 0..7
    const int cg = (lane & 3) * 2;       // 0,2,4,6
    #pragma unroll
    for (int mf = 0; mf < 4; ++mf) {
        const int rbase = row0 + wm*64 + mf*16 + rg;
        #pragma unroll
        for (int nf = 0; nf < 4; ++nf) {
            const int col = col0 + wn*32 + nf*8 + cg;
            const float2 bia = *(const float2*)(bias + col);
            float f0 = acc[mf][nf][0] + bia.x;
            float f1 = acc[mf][nf][1] + bia.y;
            float f2 = acc[mf][nf][2] + bia.x;
            float f3 = acc[mf][nf][3] + bia.y;
            if (EPI == 0) {
                const float2 r0v = *(const float2*)(resid + (size_t)rbase * Nld + col);
                const float2 r1v = *(const float2*)(resid + (size_t)(rbase+8) * Nld + col);
                *(float2*)(Cf + (size_t)rbase * Nld + col)     = make_float2(f0 + r0v.x, f1 + r0v.y);
                *(float2*)(Cf + (size_t)(rbase+8) * Nld + col) = make_float2(f2 + r1v.x, f3 + r1v.y);
            } else {
                f0 = fmaxf(f0, 0.f); f1 = fmaxf(f1, 0.f);
                f2 = fmaxf(f2, 0.f); f3 = fmaxf(f3, 0.f);
                bf16 h0 = __float2bfloat16(f0), h1 = __float2bfloat16(f1);
                bf16 h2 = __float2bfloat16(f2), h3 = __float2bfloat16(f3);
                bf16 l0 = __float2bfloat16(f0 - __bfloat162float(h0));
                bf16 l1 = __float2bfloat16(f1 - __bfloat162float(h1));
                bf16 l2 = __float2bfloat16(f2 - __bfloat162float(h2));
                bf16 l3 = __float2bfloat16(f3 - __bfloat162float(h3));
                unsigned uh0 = (unsigned)__bfloat16_as_ushort(h0) | ((unsigned)__bfloat16_as_ushort(h1) << 16);
                unsigned uh1 = (unsigned)__bfloat16_as_ushort(h2) | ((unsigned)__bfloat16_as_ushort(h3) << 16);
                unsigned ul0 = (unsigned)__bfloat16_as_ushort(l0) | ((unsigned)__bfloat16_as_ushort(l1) << 16);
                unsigned ul1 = (unsigned)__bfloat16_as_ushort(l2) | ((unsigned)__bfloat16_as_ushort(l3) << 16);
                *(unsigned*)(Chh + (size_t)rbase * Nld + col)     = uh0;
                *(unsigned*)(Chh + (size_t)(rbase+8) * Nld + col) = uh1;
                *(unsigned*)(Chl + (size_t)rbase * Nld + col)     = ul0;
                *(unsigned*)(Chl + (size_t)(rbase+8) * Nld + col) = ul1;
            }
        }
    }
}

// ================= SIMT SGEMM for the small projections =================
#define BM 128
#define BN 128
#define BKk 16
#define TM 8
#define TN 8

template<int EPI>
__global__ __launch_bounds__(256)
void sgemm_kernel(const float* __restrict__ A, int lda,
                  const float* __restrict__ W, int N_,
                  const float* __restrict__ bias,
                  const float* __restrict__ resid, int ldr,
                  float* __restrict__ C, int ldc,
                  int K)
{
    __shared__ float As[BKk][BM];
    __shared__ float Bs[BKk][BN];
    const int tid  = threadIdx.x;
    const int row0 = blockIdx.y * BM;
    const int col0 = blockIdx.x * BN;
    const int tr   = (tid >> 4) * TM;
    const int tc   = (tid & 15) * TN;

    float acc[TM][TN];
    #pragma unroll
    for (int i = 0; i < TM; ++i)
        #pragma unroll
        for (int j = 0; j < TN; ++j) acc[i][j] = 0.f;

    for (int k0 = 0; k0 < K; k0 += BKk) {
        #pragma unroll
        for (int i = 0; i < 2; ++i) {
            int idx = tid + i * 256;
            int r   = idx >> 2;
            int c   = (idx & 3) << 2;
            const float4 v = *(const float4*)(A + (size_t)(row0 + r) * lda + k0 + c);
            As[c + 0][r] = v.x; As[c + 1][r] = v.y; As[c + 2][r] = v.z; As[c + 3][r] = v.w;
        }
        #pragma unroll
        for (int i = 0; i < 2; ++i) {
            int idx = tid + i * 256;
            int r   = idx >> 5;
            int c   = (idx & 31) << 2;
            int gc  = col0 + c;
            float4 v = make_float4(0.f, 0.f, 0.f, 0.f);
            if (gc < N_) v = *(const float4*)(W + (size_t)(k0 + r) * N_ + gc);
            Bs[r][c + 0] = v.x; Bs[r][c + 1] = v.y; Bs[r][c + 2] = v.z; Bs[r][c + 3] = v.w;
        }
        __syncthreads();
        #pragma unroll
        for (int kk = 0; kk < BKk; ++kk) {
            float a[TM], bbv[TN];
            #pragma unroll
            for (int i = 0; i < TM; ++i) a[i] = As[kk][tr + i];
            #pragma unroll
            for (int j = 0; j < TN; ++j) bbv[j] = Bs[kk][tc + j];
            #pragma unroll
            for (int i = 0; i < TM; ++i)
                #pragma unroll
                for (int j = 0; j < TN; ++j) acc[i][j] += a[i] * bbv[j];
        }
        __syncthreads();
    }

    #pragma unroll
    for (int i = 0; i < TM; ++i) {
        int row = row0 + tr + i;
        #pragma unroll
        for (int j = 0; j < TN; ++j) {
            int col = col0 + tc + j;
            if (col < N_) {
                float v = acc[i][j] + bias[col];
                if (EPI == 1) v = fmaxf(v, 0.f);
                if (EPI == 2) v += resid[(size_t)row * ldr + col];
                C[(size_t)row * ldc + col] = v;
            }
        }
    }
}

// ================= fused attention (single-pass, scores tiny) =================
#define QT 128
#define KT 32
#define ATTN_SCALE 0.03125f   // 1/sqrt(1024)

__global__ __launch_bounds__(128)
void attn_kernel(const float* __restrict__ qkv, float* __restrict__ outp,
                 bf16* __restrict__ outh, bf16* __restrict__ outl)
{
    __shared__ float Ks[KT][DHd];
    __shared__ float Vs[KT][DHd];
    const int b = blockIdx.y;
    const int t = threadIdx.x;
    const int qrow = blockIdx.x * QT + t;
    const float* base = qkv + (size_t)b * Ssz * QKVW;

    float q[DHd];
    #pragma unroll
    for (int i = 0; i < 8; ++i) {
        float4 v = *(const float4*)(base + (size_t)qrow * QKVW + i * 4);
        q[i*4+0] = v.x; q[i*4+1] = v.y; q[i*4+2] = v.z; q[i*4+3] = v.w;
    }
    float o[DHd];
    #pragma unroll
    for (int d = 0; d < DHd; ++d) o[d] = 0.f;
    float l = 0.f;

    for (int k0 = 0; k0 < Ssz; k0 += KT) {
        #pragma unroll
        for (int i = 0; i < 2; ++i) {
            int idx = t + i * 128;
            int r   = idx >> 3;
            int c   = (idx & 7) << 2;
            const float* src = base + (size_t)(k0 + r) * QKVW;
            float4 kv = *(const float4*)(src + 32 + c);
            Ks[r][c+0] = kv.x; Ks[r][c+1] = kv.y; Ks[r][c+2] = kv.z; Ks[r][c+3] = kv.w;
            float4 vv = *(const float4*)(src + 64 + c);
            Vs[r][c+0] = vv.x; Vs[r][c+1] = vv.y; Vs[r][c+2] = vv.z; Vs[r][c+3] = vv.w;
        }
        __syncthreads();
        #pragma unroll 8
        for (int j = 0; j < KT; ++j) {
            float s = 0.f;
            #pragma unroll
            for (int d = 0; d < DHd; ++d) s += q[d] * Ks[j][d];
            float p = __expf(s * ATTN_SCALE);
            l += p;
            #pragma unroll
            for (int d = 0; d < DHd; ++d) o[d] += p * Vs[j][d];
        }
        __syncthreads();
    }

    const float inv = 1.f / l;
    const size_t rowoff = ((size_t)b * Ssz + qrow) * Dsz;
    float* dst = outp + rowoff;
    #pragma unroll
    for (int i = 0; i < 8; ++i) {
        float f0 = o[i*4+0]*inv, f1 = o[i*4+1]*inv, f2 = o[i*4+2]*inv, f3 = o[i*4+3]*inv;
        *(float4*)(dst + i * 4) = make_float4(f0, f1, f2, f3);
        bf16 h0 = __float2bfloat16(f0), h1 = __float2bfloat16(f1);
        bf16 h2 = __float2bfloat16(f2), h3 = __float2bfloat16(f3);
        bf16 l0 = __float2bfloat16(f0 - __bfloat162float(h0));
        bf16 l1 = __float2bfloat16(f1 - __bfloat162float(h1));
        bf16 l2 = __float2bfloat16(f2 - __bfloat162float(h2));
        bf16 l3 = __float2bfloat16(f3 - __bfloat162float(h3));
        uint2 uh, ul;
        uh.x = (unsigned)__bfloat16_as_ushort(h0) | ((unsigned)__bfloat16_as_ushort(h1) << 16);
        uh.y = (unsigned)__bfloat16_as_ushort(h2) | ((unsigned)__bfloat16_as_ushort(h3) << 16);
        ul.x = (unsigned)__bfloat16_as_ushort(l0) | ((unsigned)__bfloat16_as_ushort(l1) << 16);
        ul.y = (unsigned)__bfloat16_as_ushort(l2) | ((unsigned)__bfloat16_as_ushort(l3) << 16);
        *(uint2*)(outh + rowoff + i * 4) = uh;
        *(uint2*)(outl + rowoff + i * 4) = ul;
    }
}

// ================= LayerNorm (512, eps=1e-3), optional bf16 split emit =================
template<bool EMIT>
__global__ __launch_bounds__(128)
void ln_kernel(const float* __restrict__ y, const float* __restrict__ g,
               const float* __restrict__ be, float* __restrict__ x,
               bf16* __restrict__ xh, bf16* __restrict__ xl)
{
    const int row = blockIdx.x;
    const int t = threadIdx.x;
    const float* yr = y + (size_t)row * Dsz;
    float4 v = *(const float4*)(yr + t * 4);
    float sum = v.x + v.y + v.z + v.w;
    float sq  = v.x*v.x + v.y*v.y + v.z*v.z + v.w*v.w;
    #pragma unroll
    for (int o = 16; o > 0; o >>= 1) {
        sum += __shfl_down_sync(0xffffffffu, sum, o);
        sq  += __shfl_down_sync(0xffffffffu, sq,  o);
    }
    __shared__ float ws[4], ws2[4];
    int warp = t >> 5, lane = t & 31;
    if (lane == 0) { ws[warp] = sum; ws2[warp] = sq; }
    __syncthreads();
    if (t == 0) {
        ws[0]  = ws[0] + ws[1] + ws[2] + ws[3];
        ws2[0] = ws2[0] + ws2[1] + ws2[2] + ws2[3];
    }
    __syncthreads();
    const float mean = ws[0] * (1.f / (float)Dsz);
    const float var  = ws2[0] * (1.f / (float)Dsz) - mean * mean;
    const float r    = rsqrtf(var + 1e-3f);
    float4 gg = *(const float4*)(g + t * 4);
    float4 bb = *(const float4*)(be + t * 4);
    float4 out;
    out.x = (v.x - mean) * r * gg.x + bb.x;
    out.y = (v.y - mean) * r * gg.y + bb.y;
    out.z = (v.z - mean) * r * gg.z + bb.z;
    out.w = (v.w - mean) * r * gg.w + bb.w;
    *(float4*)(x + (size_t)row * Dsz + t * 4) = out;
    if (EMIT) {
        bf16 h0 = __float2bfloat16(out.x), h1 = __float2bfloat16(out.y);
        bf16 h2 = __float2bfloat16(out.z), h3 = __float2bfloat16(out.w);
        bf16 l0 = __float2bfloat16(out.x - __bfloat162float(h0));
        bf16 l1 = __float2bfloat16(out.y - __bfloat162float(h1));
        bf16 l2 = __float2bfloat16(out.z - __bfloat162float(h2));
        bf16 l3 = __float2bfloat16(out.w - __bfloat162float(h3));
        uint2 uh, ul;
        uh.x = (unsigned)__bfloat16_as_ushort(h0) | ((unsigned)__bfloat16_as_ushort(h1) << 16);
        uh.y = (unsigned)__bfloat16_as_ushort(h2) | ((unsigned)__bfloat16_as_ushort(h3) << 16);
        ul.x = (unsigned)__bfloat16_as_ushort(l0) | ((unsigned)__bfloat16_as_ushort(l1) << 16);
        ul.y = (unsigned)__bfloat16_as_ushort(l2) | ((unsigned)__bfloat16_as_ushort(l3) << 16);
        *(uint2*)(xh + (size_t)row * Dsz + t * 4) = uh;
        *(uint2*)(xl + (size_t)row * Dsz + t * 4) = ul;
    }
}

// ================= mean-pool + final dense + sigmoid =================
__global__ __launch_bounds__(256)
void final_kernel(const float* __restrict__ x, const float* __restrict__ Wf,
                  const float* __restrict__ bf_, float* __restrict__ out, int out_size)
{
    const int b = blockIdx.x;
    const float* xb = x + (size_t)b * Ssz * Dsz;
    float acc = 0.f;
    for (int i = threadIdx.x; i < (Ssz * Dsz) / 4; i += 256) {
        float4 v = *(const float4*)(xb + (size_t)i * 4);
        int d = (i * 4) & (Dsz - 1);
        acc += v.x * Wf[d] + v.y * Wf[d+1] + v.z * Wf[d+2] + v.w * Wf[d+3];
    }
    #pragma unroll
    for (int o = 16; o > 0; o >>= 1) acc += __shfl_down_sync(0xffffffffu, acc, o);
    __shared__ float ws[8];
    int warp = threadIdx.x >> 5, lane = threadIdx.x & 31;
    if (lane == 0) ws[warp] = acc;
    __syncthreads();
    if (threadIdx.x == 0) {
        float tot = 0.f;
        #pragma unroll
        for (int w = 0; w < 8; ++w) tot += ws[w];
        float logit = tot * (1.f / (float)Ssz) + bf_[0];
        if (b < out_size) out[b] = logit;
        if (Bsz + b < out_size) out[Bsz + b] = 1.f / (1.f + expf(-logit));
    }
}

// ================= orchestration =================
extern "C" void kernel_launch(void* const* d_in, const int* in_sizes, int n_in,
                              void* d_out, int out_size)
{
    const int*   tok = (const int*)  d_in[0];
    const float* emb = (const float*)d_in[1];
    const float* W0  = (const float*)d_in[2];
    const float* b0  = (const float*)d_in[3];
    const float* Wh  = (const float*)d_in[4];
    const float* bh  = (const float*)d_in[5];
    const float* Wo  = (const float*)d_in[6];
    const float* bo  = (const float*)d_in[7];
    const float* g1  = (const float*)d_in[8];
    const float* be1 = (const float*)d_in[9];
    const float* W1  = (const float*)d_in[10];
    const float* b1  = (const float*)d_in[11];
    const float* W2  = (const float*)d_in[12];
    const float* b2  = (const float*)d_in[13];
    const float* g2  = (const float*)d_in[14];
    const float* be2 = (const float*)d_in[15];
    const float* Wf  = (const float*)d_in[16];
    const float* bf_ = (const float*)d_in[17];
    float* out = (float*)d_out;

    float *x, *y, *xh, *qkv;
    bf16 *xhh, *xhl, *xbh, *xbl, *h1h, *h1l;
    bf16 *woth, *wotl, *w1th, *w1tl, *w2th, *w2tl;
    cudaGetSymbolAddress((void**)&x,   g_x);
    cudaGetSymbolAddress((void**)&y,   g_y);
    cudaGetSymbolAddress((void**)&xh,  g_xh);
    cudaGetSymbolAddress((void**)&qkv, g_qkv);
    cudaGetSymbolAddress((void**)&xhh, g_xhh);
    cudaGetSymbolAddress((void**)&xhl, g_xhl);
    cudaGetSymbolAddress((void**)&xbh, g_xbh);
    cudaGetSymbolAddress((void**)&xbl, g_xbl);
    cudaGetSymbolAddress((void**)&h1h, g_h1h);
    cudaGetSymbolAddress((void**)&h1l, g_h1l);
    cudaGetSymbolAddress((void**)&woth, g_woth);
    cudaGetSymbolAddress((void**)&wotl, g_wotl);
    cudaGetSymbolAddress((void**)&w1th, g_w1th);
    cudaGetSymbolAddress((void**)&w1tl, g_w1tl);
    cudaGetSymbolAddress((void**)&w2th, g_w2th);
    cudaGetSymbolAddress((void**)&w2tl, g_w2tl);

    cudaFuncSetAttribute(gemm_mma<0>, cudaFuncAttributeMaxDynamicSharedMemorySize, GDYN);
    cudaFuncSetAttribute(gemm_mma<1>, cudaFuncAttributeMaxDynamicSharedMemorySize, GDYN);

    {
        int64_t tot = (int64_t)Bsz * Ssz * Dsz;
        embed_kernel<<<(unsigned)((tot + 255) / 256), 256>>>(tok, emb, x);
    }

    // weight transpose + bf16 split (all layers)
    wsplit_kernel<<<dim3(Dsz/32, Dsz/32, NBlk), 256>>>(Wo, woth, wotl, Dsz, Dsz);
    wsplit_kernel<<<dim3(FFd/32, Dsz/32, NBlk), 256>>>(W1, w1th, w1tl, Dsz, FFd);
    wsplit_kernel<<<dim3(Dsz/32, FFd/32, NBlk), 256>>>(W2, w2th, w2tl, FFd, Dsz);

    const dim3 gemm_proj(1, MROWS / BM);
    const dim3 attn_grid(Ssz / QT, Bsz);
    const dim3 tc_wo(Dsz / GBN,  MROWS / GBM);   // (4, 256)
    const dim3 tc_f1(FFd / GBN,  MROWS / GBM);   // (16, 256)
    const dim3 tc_f2(Dsz / GBN,  MROWS / GBM);   // (4, 256)

    for (int l = 0; l < NBlk; ++l) {
        // head 0: D -> 96 (SIMT)
        sgemm_kernel<0><<<gemm_proj, 256>>>(x, Dsz,
            W0 + (size_t)l * Dsz * QKVW, QKVW, b0 + (size_t)l * QKVW,
            nullptr, 0, qkv, QKVW, Dsz);
        attn_kernel<<<attn_grid, 128>>>(qkv, xh, xhh, xhl);

        // chained heads 1..15: DH -> 96 (SIMT)
        for (int h = 1; h < Hh; ++h) {
            const float* Whl = Wh + ((size_t)l * (Hh - 1) + (h - 1)) * DHd * QKVW;
            const float* bhl = bh + ((size_t)l * (Hh - 1) + (h - 1)) * QKVW;
            sgemm_kernel<0><<<gemm_proj, 256>>>(xh + (size_t)(h - 1) * DHd, Dsz,
                Whl, QKVW, bhl, nullptr, 0, qkv, QKVW, DHd);
            attn_kernel<<<attn_grid, 128>>>(qkv,
                xh + (size_t)h * DHd, xhh + (size_t)h * DHd, xhl + (size_t)h * DHd);
        }

        // output projection + residual (mma), then LN1 (emit bf16)
        gemm_mma<0><<<tc_wo, 256, GDYN>>>(xhh, xhl,
            woth + (size_t)l * Dsz * Dsz, wotl + (size_t)l * Dsz * Dsz,
            bo + (size_t)l * Dsz, x, y, nullptr, nullptr, Dsz, Dsz);
        ln_kernel<true><<<MROWS, 128>>>(y, g1 + (size_t)l * Dsz, be1 + (size_t)l * Dsz,
                                        x, xbh, xbl);

        // FFN1 (mma, relu -> bf16 split)
        gemm_mma<1><<<tc_f1, 256, GDYN>>>(xbh, xbl,
            w1th + (size_t)l * FFd * Dsz, w1tl + (size_t)l * FFd * Dsz,
            b1 + (size_t)l * FFd, nullptr, nullptr, h1h, h1l, Dsz, FFd);

        // FFN2 (mma) + residual, then LN2
        gemm_mma<0><<<tc_f2, 256, GDYN>>>(h1h, h1l,
            w2th + (size_t)l * Dsz * FFd, w2tl + (size_t)l * Dsz * FFd,
            b2 + (size_t)l * Dsz, x, y, nullptr, nullptr, FFd, Dsz);
        ln_kernel<false><<<MROWS, 128>>>(y, g2 + (size_t)l * Dsz, be2 + (size_t)l * Dsz,
                                         x, nullptr, nullptr);
    }

    final_kernel<<<Bsz, 256>>>(x, Wf, bf_, out, out_size);
}

// round 5
// speedup vs baseline: 2.8448x; 1.7320x over previous
#include <cuda_runtime.h>
#include <cuda_bf16.h>
#include <math.h>
#include <stdint.h>

// Problem dims
#define Bsz   32
#define Ssz   1024
#define Dsz   512
#define Hh    16
#define NBlk  12
#define DHd   32
#define FFd   2048
#define MROWS (Bsz*Ssz)            // 32768
#define QKVW  96                   // 3*DHd

typedef __nv_bfloat16 bf16;

// ---------------- scratch (allocation-free: __device__ globals) ----------------
__device__ float g_x  [(size_t)MROWS*Dsz];    // current activations (fp32)
__device__ float g_y  [(size_t)MROWS*Dsz];    // pre-LN temp
__device__ float g_xh [(size_t)MROWS*Dsz];    // concat of head outputs (fp32)
__device__ bf16  g_qkvh[(size_t)MROWS*QKVW];  // per-head q|k|v bf16 hi
__device__ bf16  g_qkvl[(size_t)MROWS*QKVW];  // per-head q|k|v bf16 lo
__device__ bf16  g_xhh[(size_t)MROWS*Dsz];    // xh bf16 hi
__device__ bf16  g_xhl[(size_t)MROWS*Dsz];    // xh bf16 lo
__device__ bf16  g_xbh[(size_t)MROWS*Dsz];    // x (post-LN1) bf16 hi
__device__ bf16  g_xbl[(size_t)MROWS*Dsz];    // x (post-LN1) bf16 lo
__device__ bf16  g_h1h[(size_t)MROWS*FFd];    // ffn hidden bf16 hi
__device__ bf16  g_h1l[(size_t)MROWS*FFd];    // ffn hidden bf16 lo
__device__ bf16  g_woth[(size_t)NBlk*Dsz*Dsz];   // Wo^T bf16 hi   [N=512,K=512]
__device__ bf16  g_wotl[(size_t)NBlk*Dsz*Dsz];
__device__ bf16  g_w1th[(size_t)NBlk*FFd*Dsz];   // W1^T           [N=2048,K=512]
__device__ bf16  g_w1tl[(size_t)NBlk*FFd*Dsz];
__device__ bf16  g_w2th[(size_t)NBlk*Dsz*FFd];   // W2^T           [N=512,K=2048]
__device__ bf16  g_w2tl[(size_t)NBlk*Dsz*FFd];

// ================= low-level helpers =================
__device__ __forceinline__ uint32_t smem_u32(const void* p) {
    uint32_t a;
    asm("{ .reg .u64 t; cvta.to.shared.u64 t, %1; cvt.u32.u64 %0, t; }" : "=r"(a) : "l"(p));
    return a;
}
static __device__ __forceinline__ uint32_t swz128(uint32_t off) { return off ^ ((off >> 3) & 0x70u); }

__device__ __forceinline__ void cp16(uint32_t smem, const void* gmem) {
    asm volatile("cp.async.cg.shared.global [%0], [%1], 16;" :: "r"(smem), "l"(gmem));
}
__device__ __forceinline__ void cp_commit() { asm volatile("cp.async.commit_group;"); }
__device__ __forceinline__ void cp_wait0() { asm volatile("cp.async.wait_group 0;"); }
__device__ __forceinline__ void cp_wait1() { asm volatile("cp.async.wait_group 1;"); }

__device__ __forceinline__ void ldm_x4(uint32_t addr, uint32_t& r0, uint32_t& r1, uint32_t& r2, uint32_t& r3) {
    asm volatile("ldmatrix.sync.aligned.m8n8.x4.shared.b16 {%0,%1,%2,%3}, [%4];"
                 : "=r"(r0), "=r"(r1), "=r"(r2), "=r"(r3) : "r"(addr));
}
__device__ __forceinline__ void ldm_x4t(uint32_t addr, uint32_t& r0, uint32_t& r1, uint32_t& r2, uint32_t& r3) {
    asm volatile("ldmatrix.sync.aligned.m8n8.x4.trans.shared.b16 {%0,%1,%2,%3}, [%4];"
                 : "=r"(r0), "=r"(r1), "=r"(r2), "=r"(r3) : "r"(addr));
}
__device__ __forceinline__ void mma16816(float* c, uint32_t a0, uint32_t a1, uint32_t a2, uint32_t a3,
                                         uint32_t b0, uint32_t b1) {
    asm volatile("mma.sync.aligned.m16n8k16.row.col.f32.bf16.bf16.f32 "
                 "{%0,%1,%2,%3}, {%4,%5,%6,%7}, {%8,%9}, {%0,%1,%2,%3};"
                 : "+f"(c[0]), "+f"(c[1]), "+f"(c[2]), "+f"(c[3])
                 : "r"(a0), "r"(a1), "r"(a2), "r"(a3), "r"(b0), "r"(b1));
}
__device__ __forceinline__ unsigned pack_hi(float a, float b) {
    bf16 h0 = __float2bfloat16(a), h1 = __float2bfloat16(b);
    return (unsigned)__bfloat16_as_ushort(h0) | ((unsigned)__bfloat16_as_ushort(h1) << 16);
}
__device__ __forceinline__ unsigned pack_lo(float a, float b) {
    bf16 h0 = __float2bfloat16(a), h1 = __float2bfloat16(b);
    bf16 l0 = __float2bfloat16(a - __bfloat162float(h0));
    bf16 l1 = __float2bfloat16(b - __bfloat162float(h1));
    return (unsigned)__bfloat16_as_ushort(l0) | ((unsigned)__bfloat16_as_ushort(l1) << 16);
}

// ================= embedding + positional encoding =================
__global__ void embed_kernel(const int* __restrict__ tok,
                             const float* __restrict__ emb,
                             float* __restrict__ x)
{
    int64_t i = (int64_t)blockIdx.x * blockDim.x + threadIdx.x;
    if (i >= (int64_t)Bsz * Ssz * Dsz) return;
    int d      = (int)(i & (Dsz - 1));
    int64_t bs = i >> 9;
    int s      = (int)(bs & (Ssz - 1));
    int t      = tok[bs];
    int j      = d >> 1;
    float e    = (2.0f * (float)j) / (float)Dsz;
    float freq = expf(-e * 9.210340371976184f);
    float ang  = (float)s * freq;
    float p    = (d & 1) ? cosf(ang) : sinf(ang);
    x[i] = emb[(int64_t)t * Dsz + d] + p;
}

// ================= weight transpose + bf16 split =================
__global__ __launch_bounds__(256)
void wsplit_kernel(const float* __restrict__ W, bf16* __restrict__ Th, bf16* __restrict__ Tl,
                   int K, int N)
{
    __shared__ float t[32][33];
    int z = blockIdx.z;
    const float* Wz = W + (size_t)z * K * N;
    bf16* Thz = Th + (size_t)z * K * N;
    bf16* Tlz = Tl + (size_t)z * K * N;
    int n0 = blockIdx.x * 32, k0 = blockIdx.y * 32;
    int tx = threadIdx.x & 31, ty = threadIdx.x >> 5;
    #pragma unroll
    for (int i = 0; i < 4; ++i)
        t[ty + i*8][tx] = Wz[(size_t)(k0 + ty + i*8) * N + n0 + tx];
    __syncthreads();
    #pragma unroll
    for (int i = 0; i < 4; ++i) {
        float v = t[tx][ty + i*8];
        bf16 h = __float2bfloat16(v);
        bf16 lo = __float2bfloat16(v - __bfloat162float(h));
        size_t o = (size_t)(n0 + ty + i*8) * K + k0 + tx;
        Thz[o] = h; Tlz[o] = lo;
    }
}

// ================= mma.sync bf16-split GEMM (big GEMMs) =================
#define GBM 128
#define GBN 128
#define GBK 64
#define ST_AH 0
#define ST_AL 16384
#define ST_BH 32768
#define ST_BL 49152
#define STAGE_BYTES 65536
#define GDYN (2*STAGE_BYTES)

template<int EPI>
__global__ __launch_bounds__(256, 1)
void gemm_mma(const bf16* __restrict__ Ah, const bf16* __restrict__ Al,
              const bf16* __restrict__ Bh, const bf16* __restrict__ Bl,
              const float* __restrict__ bias,
              const float* __restrict__ resid,
              float* __restrict__ Cf,
              bf16* __restrict__ Chh, bf16* __restrict__ Chl,
              int K, int Nld)
{
    extern __shared__ char dsm[];
    const uint32_t sb = smem_u32(dsm);

    const int tid  = threadIdx.x;
    const int lane = tid & 31;
    const int w    = tid >> 5;
    const int wm   = w >> 2;
    const int wn   = w & 3;
    const int row0 = blockIdx.y * GBM;
    const int col0 = blockIdx.x * GBN;

    const int lr = tid >> 3;
    const int lc = tid & 7;
    const size_t  lgo = (size_t)lr * K + lc * 8;

    float acc[4][4][4];
    #pragma unroll
    for (int i = 0; i < 4; ++i)
        #pragma unroll
        for (int j = 0; j < 4; ++j)
            #pragma unroll
            for (int k = 0; k < 4; ++k) acc[i][j][k] = 0.f;

    const int nchunks = K / GBK;

    auto load_stage = [&](int c, int st) {
        const uint32_t s0 = sb + st * STAGE_BYTES;
        const size_t kofs = (size_t)c * GBK;
        const size_t ga = (size_t)row0 * K + kofs + lgo;
        const size_t gb = (size_t)col0 * K + kofs + lgo;
        #pragma unroll
        for (int i = 0; i < 4; ++i) {
            uint32_t so = swz128((uint32_t)((lr + i*32) * 128 + lc * 16));
            size_t   go = (size_t)(i*32) * K;
            cp16(s0 + ST_AH + so, Ah + ga + go);
            cp16(s0 + ST_AL + so, Al + ga + go);
            cp16(s0 + ST_BH + so, Bh + gb + go);
            cp16(s0 + ST_BL + so, Bl + gb + go);
        }
        cp_commit();
    };

    load_stage(0, 0);

    for (int c = 0; c < nchunks; ++c) {
        const int st = c & 1;
        if (c + 1 < nchunks) { load_stage(c + 1, st ^ 1); cp_wait1(); }
        else                 { cp_wait0(); }
        __syncthreads();

        const uint32_t s0 = sb + st * STAGE_BYTES;
        const int arow = wm * 64 + (lane & 15);
        const int acolb = (lane >> 4) << 4;
        const int nrow = wn * 32 + ((lane >> 4) << 3) + (lane & 7);
        const int bcolb = ((lane >> 3) & 1) << 4;

        #pragma unroll
        for (int slab = 0; slab < 4; ++slab) {
            const int kb = slab * 32;
            uint32_t ah[4][4], al[4][4], bh[2][4], bl[2][4];
            #pragma unroll
            for (int mf = 0; mf < 4; ++mf) {
                uint32_t ao = swz128((uint32_t)((arow + mf*16) * 128 + kb + acolb));
                ldm_x4(s0 + ST_AH + ao, ah[mf][0], ah[mf][1], ah[mf][2], ah[mf][3]);
                ldm_x4(s0 + ST_AL + ao, al[mf][0], al[mf][1], al[mf][2], al[mf][3]);
            }
            #pragma unroll
            for (int ng = 0; ng < 2; ++ng) {
                uint32_t bo = swz128((uint32_t)((nrow + ng*16) * 128 + kb + bcolb));
                ldm_x4(s0 + ST_BH + bo, bh[ng][0], bh[ng][1], bh[ng][2], bh[ng][3]);
                ldm_x4(s0 + ST_BL + bo, bl[ng][0], bl[ng][1], bl[ng][2], bl[ng][3]);
            }
            #pragma unroll
            for (int mf = 0; mf < 4; ++mf) {
                #pragma unroll
                for (int ng = 0; ng < 2; ++ng) {
                    mma16816(acc[mf][2*ng],   ah[mf][0], ah[mf][1], ah[mf][2], ah[mf][3], bh[ng][0], bh[ng][1]);
                    mma16816(acc[mf][2*ng+1], ah[mf][0], ah[mf][1], ah[mf][2], ah[mf][3], bh[ng][2], bh[ng][3]);
                    mma16816(acc[mf][2*ng],   ah[mf][0], ah[mf][1], ah[mf][2], ah[mf][3], bl[ng][0], bl[ng][1]);
                    mma16816(acc[mf][2*ng+1], ah[mf][0], ah[mf][1], ah[mf][2], ah[mf][3], bl[ng][2], bl[ng][3]);
                    mma16816(acc[mf][2*ng],   al[mf][0], al[mf][1], al[mf][2], al[mf][3], bh[ng][0], bh[ng][1]);
                    mma16816(acc[mf][2*ng+1], al[mf][0], al[mf][1], al[mf][2], al[mf][3], bh[ng][2], bh[ng][3]);
                }
            }
        }
        __syncthreads();
    }

    const int rg = lane >> 2;
    const int cg = (lane & 3) * 2;
    #pragma unroll
    for (int mf = 0; mf < 4; ++mf) {
        const int rbase = row0 + wm*64 + mf*16 + rg;
        #pragma unroll
        for (int nf = 0; nf < 4; ++nf) {
            const int col = col0 + wn*32 + nf*8 + cg;
            const float2 bia = *(const float2*)(bias + col);
            float f0 = acc[mf][nf][0] + bia.x;
            float f1 = acc[mf][nf][1] + bia.y;
            float f2 = acc[mf][nf][2] + bia.x;
            float f3 = acc[mf][nf][3] + bia.y;
            if (EPI == 0) {
                const float2 r0v = *(const float2*)(resid + (size_t)rbase * Nld + col);
                const float2 r1v = *(const float2*)(resid + (size_t)(rbase+8) * Nld + col);
                *(float2*)(Cf + (size_t)rbase * Nld + col)     = make_float2(f0 + r0v.x, f1 + r0v.y);
                *(float2*)(Cf + (size_t)(rbase+8) * Nld + col) = make_float2(f2 + r1v.x, f3 + r1v.y);
            } else {
                f0 = fmaxf(f0, 0.f); f1 = fmaxf(f1, 0.f);
                f2 = fmaxf(f2, 0.f); f3 = fmaxf(f3, 0.f);
                *(unsigned*)(Chh + (size_t)rbase * Nld + col)     = pack_hi(f0, f1);
                *(unsigned*)(Chh + (size_t)(rbase+8) * Nld + col) = pack_hi(f2, f3);
                *(unsigned*)(Chl + (size_t)rbase * Nld + col)     = pack_lo(f0, f1);
                *(unsigned*)(Chl + (size_t)(rbase+8) * Nld + col) = pack_lo(f2, f3);
            }
        }
    }
}

// ================= SIMT SGEMM for the small projections =================
#define BM 128
#define BN 128
#define BKk 16
#define TM 8
#define TN 8

// EPI 3: bf16 hi/lo output (qkv projections)
template<int EPI>
__global__ __launch_bounds__(256)
void sgemm_kernel(const float* __restrict__ A, int lda,
                  const float* __restrict__ W, int N_,
                  const float* __restrict__ bias,
                  float* __restrict__ C, int ldc,
                  bf16* __restrict__ Chh, bf16* __restrict__ Chl,
                  int K)
{
    __shared__ float As[BKk][BM];
    __shared__ float Bs[BKk][BN];
    const int tid  = threadIdx.x;
    const int row0 = blockIdx.y * BM;
    const int col0 = blockIdx.x * BN;
    const int tr   = (tid >> 4) * TM;
    const int tc   = (tid & 15) * TN;

    float acc[TM][TN];
    #pragma unroll
    for (int i = 0; i < TM; ++i)
        #pragma unroll
        for (int j = 0; j < TN; ++j) acc[i][j] = 0.f;

    for (int k0 = 0; k0 < K; k0 += BKk) {
        #pragma unroll
        for (int i = 0; i < 2; ++i) {
            int idx = tid + i * 256;
            int r   = idx >> 2;
            int c   = (idx & 3) << 2;
            const float4 v = *(const float4*)(A + (size_t)(row0 + r) * lda + k0 + c);
            As[c + 0][r] = v.x; As[c + 1][r] = v.y; As[c + 2][r] = v.z; As[c + 3][r] = v.w;
        }
        #pragma unroll
        for (int i = 0; i < 2; ++i) {
            int idx = tid + i * 256;
            int r   = idx >> 5;
            int c   = (idx & 31) << 2;
            int gc  = col0 + c;
            float4 v = make_float4(0.f, 0.f, 0.f, 0.f);
            if (gc < N_) v = *(const float4*)(W + (size_t)(k0 + r) * N_ + gc);
            Bs[r][c + 0] = v.x; Bs[r][c + 1] = v.y; Bs[r][c + 2] = v.z; Bs[r][c + 3] = v.w;
        }
        __syncthreads();
        #pragma unroll
        for (int kk = 0; kk < BKk; ++kk) {
            float a[TM], bbv[TN];
            #pragma unroll
            for (int i = 0; i < TM; ++i) a[i] = As[kk][tr + i];
            #pragma unroll
            for (int j = 0; j < TN; ++j) bbv[j] = Bs[kk][tc + j];
            #pragma unroll
            for (int i = 0; i < TM; ++i)
                #pragma unroll
                for (int j = 0; j < TN; ++j) acc[i][j] += a[i] * bbv[j];
        }
        __syncthreads();
    }

    #pragma unroll
    for (int i = 0; i < TM; ++i) {
        int row = row0 + tr + i;
        if (EPI == 3) {
            #pragma unroll
            for (int j = 0; j < TN; j += 2) {
                int col = col0 + tc + j;
                if (col < N_) {
                    float f0 = acc[i][j]   + bias[col];
                    float f1 = acc[i][j+1] + bias[col+1];
                    *(unsigned*)(Chh + (size_t)row * ldc + col) = pack_hi(f0, f1);
                    *(unsigned*)(Chl + (size_t)row * ldc + col) = pack_lo(f0, f1);
                }
            }
        } else {
            #pragma unroll
            for (int j = 0; j < TN; ++j) {
                int col = col0 + tc + j;
                if (col < N_) C[(size_t)row * ldc + col] = acc[i][j] + bias[col];
            }
        }
    }
}

// ================= mma.sync flash attention (single-pass, scores tiny) =================
#define ATTN_SCALE 0.03125f   // 1/sqrt(1024)
#define ATRS 80               // padded row stride bytes (32 bf16 data + 16B pad)
#define AQH 0
#define AQL 10240
#define AKV0 20480
#define AKVSTG 20480
#define AOKH 0
#define AOKL 5120
#define AOVH 10240
#define AOVL 15360
#define ATTN_DYN 61440

__global__ __launch_bounds__(128)
void attn_mma(const bf16* __restrict__ qkvh, const bf16* __restrict__ qkvl,
              float* __restrict__ outp, bf16* __restrict__ outh, bf16* __restrict__ outl)
{
    extern __shared__ char asmem[];
    const uint32_t sb = smem_u32(asmem);
    const int tid = threadIdx.x, lane = tid & 31, w = tid >> 5;
    const int b = blockIdx.y;
    const int q0 = blockIdx.x * 128;
    const size_t base = (size_t)b * Ssz * QKVW;

    // stage Q (hi/lo): 128 rows x 4x16B chunks each
    #pragma unroll
    for (int i = 0; i < 4; ++i) {
        int idx = tid + i * 128;
        int r = idx >> 2, c = idx & 3;
        size_t g = base + (size_t)(q0 + r) * QKVW + c * 8;
        cp16(sb + AQH + r * ATRS + c * 16, qkvh + g);
        cp16(sb + AQL + r * ATRS + c * 16, qkvl + g);
    }
    cp_commit();
    // KV chunk 0
    {
        const uint32_t s0 = sb + AKV0;
        #pragma unroll
        for (int i = 0; i < 2; ++i) {
            int idx = tid + i * 128;
            int r = idx >> 2, c = idx & 3;
            size_t gk = base + (size_t)r * QKVW + 32 + c * 8;
            cp16(s0 + AOKH + r * ATRS + c * 16, qkvh + gk);
            cp16(s0 + AOKL + r * ATRS + c * 16, qkvl + gk);
            cp16(s0 + AOVH + r * ATRS + c * 16, qkvh + gk + 32);
            cp16(s0 + AOVL + r * ATRS + c * 16, qkvl + gk + 32);
        }
        cp_commit();
    }
    cp_wait1();           // Q complete
    __syncthreads();

    // Q fragments: [mf][kslab][4]
    uint32_t qh[2][2][4], ql[2][2][4];
    #pragma unroll
    for (int mf = 0; mf < 2; ++mf)
        #pragma unroll
        for (int ks = 0; ks < 2; ++ks) {
            uint32_t ad = sb + (uint32_t)((w * 32 + mf * 16 + (lane & 15)) * ATRS + ks * 32 + ((lane >> 4) << 4));
            ldm_x4(ad + AQH, qh[mf][ks][0], qh[mf][ks][1], qh[mf][ks][2], qh[mf][ks][3]);
            ldm_x4(ad + AQL, ql[mf][ks][0], ql[mf][ks][1], ql[mf][ks][2], ql[mf][ks][3]);
        }

    float o[2][4][4];
    float lsum[2][2];
    #pragma unroll
    for (int mf = 0; mf < 2; ++mf) {
        lsum[mf][0] = 0.f; lsum[mf][1] = 0.f;
        #pragma unroll
        for (int n8 = 0; n8 < 4; ++n8)
            #pragma unroll
            for (int j = 0; j < 4; ++j) o[mf][n8][j] = 0.f;
    }

    for (int c = 0; c < 16; ++c) {
        const int st = c & 1;
        if (c < 15) {
            const uint32_t s1 = sb + AKV0 + (st ^ 1) * AKVSTG;
            #pragma unroll
            for (int i = 0; i < 2; ++i) {
                int idx = tid + i * 128;
                int r = idx >> 2, cc = idx & 3;
                size_t gk = base + (size_t)((c + 1) * 64 + r) * QKVW + 32 + cc * 8;
                cp16(s1 + AOKH + r * ATRS + cc * 16, qkvh + gk);
                cp16(s1 + AOKL + r * ATRS + cc * 16, qkvl + gk);
                cp16(s1 + AOVH + r * ATRS + cc * 16, qkvh + gk + 32);
                cp16(s1 + AOVL + r * ATRS + cc * 16, qkvl + gk + 32);
            }
            cp_commit(); cp_wait1();
        } else cp_wait0();
        __syncthreads();

        const uint32_t kb = sb + AKV0 + st * AKVSTG;

        #pragma unroll
        for (int g = 0; g < 4; ++g) {
            // ---- S = Q K^T for 16 keys (g-th n16 group == k16 slab of P) ----
            float s[2][2][4];
            #pragma unroll
            for (int mf = 0; mf < 2; ++mf)
                #pragma unroll
                for (int f = 0; f < 2; ++f)
                    #pragma unroll
                    for (int j = 0; j < 4; ++j) s[mf][f][j] = 0.f;

            #pragma unroll
            for (int ks = 0; ks < 2; ++ks) {
                uint32_t kh[4], kl[4];
                uint32_t ad = kb + (uint32_t)((g * 16 + ((lane >> 4) << 3) + (lane & 7)) * ATRS
                                              + ks * 32 + (((lane >> 3) & 1) << 4));
                ldm_x4(ad + AOKH, kh[0], kh[1], kh[2], kh[3]);
                ldm_x4(ad + AOKL, kl[0], kl[1], kl[2], kl[3]);
                #pragma unroll
                for (int mf = 0; mf < 2; ++mf) {
                    mma16816(s[mf][0], qh[mf][ks][0], qh[mf][ks][1], qh[mf][ks][2], qh[mf][ks][3], kh[0], kh[1]);
                    mma16816(s[mf][1], qh[mf][ks][0], qh[mf][ks][1], qh[mf][ks][2], qh[mf][ks][3], kh[2], kh[3]);
                    mma16816(s[mf][0], qh[mf][ks][0], qh[mf][ks][1], qh[mf][ks][2], qh[mf][ks][3], kl[0], kl[1]);
                    mma16816(s[mf][1], qh[mf][ks][0], qh[mf][ks][1], qh[mf][ks][2], qh[mf][ks][3], kl[2], kl[3]);
                    mma16816(s[mf][0], ql[mf][ks][0], ql[mf][ks][1], ql[mf][ks][2], ql[mf][ks][3], kh[0], kh[1]);
                    mma16816(s[mf][1], ql[mf][ks][0], ql[mf][ks][1], ql[mf][ks][2], ql[mf][ks][3], kh[2], kh[3]);
                }
            }

            // ---- p = exp(s*scale), row sums, pack P hi/lo as A-fragments ----
            uint32_t ph[2][4], pl[2][4];
            #pragma unroll
            for (int mf = 0; mf < 2; ++mf) {
                float p[2][4];
                #pragma unroll
                for (int f = 0; f < 2; ++f)
                    #pragma unroll
                    for (int j = 0; j < 4; ++j)
                        p[f][j] = __expf(s[mf][f][j] * ATTN_SCALE);
                lsum[mf][0] += p[0][0] + p[0][1] + p[1][0] + p[1][1];
                lsum[mf][1] += p[0][2] + p[0][3] + p[1][2] + p[1][3];
                #pragma unroll
                for (int f = 0; f < 2; ++f) {
                    ph[mf][2*f]   = pack_hi(p[f][0], p[f][1]);
                    ph[mf][2*f+1] = pack_hi(p[f][2], p[f][3]);
                    pl[mf][2*f]   = pack_lo(p[f][0], p[f][1]);
                    pl[mf][2*f+1] = pack_lo(p[f][2], p[f][3]);
                }
            }

            // ---- V fragments via ldmatrix.trans, O += P V ----
            uint32_t vh[2][4], vl[2][4];
            #pragma unroll
            for (int nw = 0; nw < 2; ++nw) {
                uint32_t ad = kb + (uint32_t)((g * 16 + ((lane >> 3) & 1) * 8 + (lane & 7)) * ATRS
                                              + nw * 32 + ((lane >> 4) << 4));
                ldm_x4t(ad + AOVH, vh[nw][0], vh[nw][1], vh[nw][2], vh[nw][3]);
                ldm_x4t(ad + AOVL, vl[nw][0], vl[nw][1], vl[nw][2], vl[nw][3]);
            }
            #pragma unroll
            for (int mf = 0; mf < 2; ++mf)
                #pragma unroll
                for (int n8 = 0; n8 < 4; ++n8) {
                    const int nw = n8 >> 1, pr = (n8 & 1) * 2;
                    mma16816(o[mf][n8], ph[mf][0], ph[mf][1], ph[mf][2], ph[mf][3], vh[nw][pr], vh[nw][pr+1]);
                    mma16816(o[mf][n8], ph[mf][0], ph[mf][1], ph[mf][2], ph[mf][3], vl[nw][pr], vl[nw][pr+1]);
                    mma16816(o[mf][n8], pl[mf][0], pl[mf][1], pl[mf][2], pl[mf][3], vh[nw][pr], vh[nw][pr+1]);
                }
        }
        __syncthreads();
    }

    // ---- reduce row sums across the 4-lane column group, normalize, store ----
    #pragma unroll
    for (int mf = 0; mf < 2; ++mf)
        #pragma unroll
        for (int hh = 0; hh < 2; ++hh) {
            float v = lsum[mf][hh];
            v += __shfl_xor_sync(0xffffffffu, v, 1);
            v += __shfl_xor_sync(0xffffffffu, v, 2);
            lsum[mf][hh] = 1.f / v;
        }
    const int rg = lane >> 2, cg = (lane & 3) * 2;
    #pragma unroll
    for (int mf = 0; mf < 2; ++mf) {
        const int r0 = q0 + w * 32 + mf * 16 + rg;
        #pragma unroll
        for (int n8 = 0; n8 < 4; ++n8) {
            const int col = n8 * 8 + cg;
            float f0 = o[mf][n8][0] * lsum[mf][0];
            float f1 = o[mf][n8][1] * lsum[mf][0];
            float f2 = o[mf][n8][2] * lsum[mf][1];
            float f3 = o[mf][n8][3] * lsum[mf][1];
            size_t off0 = ((size_t)b * Ssz + r0) * Dsz + col;
            size_t off1 = off0 + (size_t)8 * Dsz;
            *(float2*)(outp + off0) = make_float2(f0, f1);
            *(float2*)(outp + off1) = make_float2(f2, f3);
            *(unsigned*)(outh + off0) = pack_hi(f0, f1);
            *(unsigned*)(outh + off1) = pack_hi(f2, f3);
            *(unsigned*)(outl + off0) = pack_lo(f0, f1);
            *(unsigned*)(outl + off1) = pack_lo(f2, f3);
        }
    }
}

// ================= LayerNorm (512, eps=1e-3), optional bf16 split emit =================
template<bool EMIT>
__global__ __launch_bounds__(128)
void ln_kernel(const float* __restrict__ y, const float* __restrict__ g,
               const float* __restrict__ be, float* __restrict__ x,
               bf16* __restrict__ xh, bf16* __restrict__ xl)
{
    const int row = blockIdx.x;
    const int t = threadIdx.x;
    const float* yr = y + (size_t)row * Dsz;
    float4 v = *(const float4*)(yr + t * 4);
    float sum = v.x + v.y + v.z + v.w;
    float sq  = v.x*v.x + v.y*v.y + v.z*v.z + v.w*v.w;
    #pragma unroll
    for (int o = 16; o > 0; o >>= 1) {
        sum += __shfl_down_sync(0xffffffffu, sum, o);
        sq  += __shfl_down_sync(0xffffffffu, sq,  o);
    }
    __shared__ float ws[4], ws2[4];
    int warp = t >> 5, lane = t & 31;
    if (lane == 0) { ws[warp] = sum; ws2[warp] = sq; }
    __syncthreads();
    if (t == 0) {
        ws[0]  = ws[0] + ws[1] + ws[2] + ws[3];
        ws2[0] = ws2[0] + ws2[1] + ws2[2] + ws2[3];
    }
    __syncthreads();
    const float mean = ws[0] * (1.f / (float)Dsz);
    const float var  = ws2[0] * (1.f / (float)Dsz) - mean * mean;
    const float r    = rsqrtf(var + 1e-3f);
    float4 gg = *(const float4*)(g + t * 4);
    float4 bb = *(const float4*)(be + t * 4);
    float4 out;
    out.x = (v.x - mean) * r * gg.x + bb.x;
    out.y = (v.y - mean) * r * gg.y + bb.y;
    out.z = (v.z - mean) * r * gg.z + bb.z;
    out.w = (v.w - mean) * r * gg.w + bb.w;
    *(float4*)(x + (size_t)row * Dsz + t * 4) = out;
    if (EMIT) {
        uint2 uh, ul;
        uh.x = pack_hi(out.x, out.y); uh.y = pack_hi(out.z, out.w);
        ul.x = pack_lo(out.x, out.y); ul.y = pack_lo(out.z, out.w);
        *(uint2*)(xh + (size_t)row * Dsz + t * 4) = uh;
        *(uint2*)(xl + (size_t)row * Dsz + t * 4) = ul;
    }
}

// ================= mean-pool + final dense + sigmoid =================
__global__ __launch_bounds__(256)
void final_kernel(const float* __restrict__ x, const float* __restrict__ Wf,
                  const float* __restrict__ bf_, float* __restrict__ out, int out_size)
{
    const int b = blockIdx.x;
    const float* xb = x + (size_t)b * Ssz * Dsz;
    float acc = 0.f;
    for (int i = threadIdx.x; i < (Ssz * Dsz) / 4; i += 256) {
        float4 v = *(const float4*)(xb + (size_t)i * 4);
        int d = (i * 4) & (Dsz - 1);
        acc += v.x * Wf[d] + v.y * Wf[d+1] + v.z * Wf[d+2] + v.w * Wf[d+3];
    }
    #pragma unroll
    for (int o = 16; o > 0; o >>= 1) acc += __shfl_down_sync(0xffffffffu, acc, o);
    __shared__ float ws[8];
    int warp = threadIdx.x >> 5, lane = threadIdx.x & 31;
    if (lane == 0) ws[warp] = acc;
    __syncthreads();
    if (threadIdx.x == 0) {
        float tot = 0.f;
        #pragma unroll
        for (int w = 0; w < 8; ++w) tot += ws[w];
        float logit = tot * (1.f / (float)Ssz) + bf_[0];
        if (b < out_size) out[b] = logit;
        if (Bsz + b < out_size) out[Bsz + b] = 1.f / (1.f + expf(-logit));
    }
}

// ================= orchestration =================
extern "C" void kernel_launch(void* const* d_in, const int* in_sizes, int n_in,
                              void* d_out, int out_size)
{
    const int*   tok = (const int*)  d_in[0];
    const float* emb = (const float*)d_in[1];
    const float* W0  = (const float*)d_in[2];
    const float* b0  = (const float*)d_in[3];
    const float* Wh  = (const float*)d_in[4];
    const float* bh  = (const float*)d_in[5];
    const float* Wo  = (const float*)d_in[6];
    const float* bo  = (const float*)d_in[7];
    const float* g1  = (const float*)d_in[8];
    const float* be1 = (const float*)d_in[9];
    const float* W1  = (const float*)d_in[10];
    const float* b1  = (const float*)d_in[11];
    const float* W2  = (const float*)d_in[12];
    const float* b2  = (const float*)d_in[13];
    const float* g2  = (const float*)d_in[14];
    const float* be2 = (const float*)d_in[15];
    const float* Wf  = (const float*)d_in[16];
    const float* bf_ = (const float*)d_in[17];
    float* out = (float*)d_out;

    float *x, *y, *xh;
    bf16 *qkvh, *qkvl, *xhh, *xhl, *xbh, *xbl, *h1h, *h1l;
    bf16 *woth, *wotl, *w1th, *w1tl, *w2th, *w2tl;
    cudaGetSymbolAddress((void**)&x,    g_x);
    cudaGetSymbolAddress((void**)&y,    g_y);
    cudaGetSymbolAddress((void**)&xh,   g_xh);
    cudaGetSymbolAddress((void**)&qkvh, g_qkvh);
    cudaGetSymbolAddress((void**)&qkvl, g_qkvl);
    cudaGetSymbolAddress((void**)&xhh,  g_xhh);
    cudaGetSymbolAddress((void**)&xhl,  g_xhl);
    cudaGetSymbolAddress((void**)&xbh,  g_xbh);
    cudaGetSymbolAddress((void**)&xbl,  g_xbl);
    cudaGetSymbolAddress((void**)&h1h,  g_h1h);
    cudaGetSymbolAddress((void**)&h1l,  g_h1l);
    cudaGetSymbolAddress((void**)&woth, g_woth);
    cudaGetSymbolAddress((void**)&wotl, g_wotl);
    cudaGetSymbolAddress((void**)&w1th, g_w1th);
    cudaGetSymbolAddress((void**)&w1tl, g_w1tl);
    cudaGetSymbolAddress((void**)&w2th, g_w2th);
    cudaGetSymbolAddress((void**)&w2tl, g_w2tl);

    cudaFuncSetAttribute(gemm_mma<0>, cudaFuncAttributeMaxDynamicSharedMemorySize, GDYN);
    cudaFuncSetAttribute(gemm_mma<1>, cudaFuncAttributeMaxDynamicSharedMemorySize, GDYN);
    cudaFuncSetAttribute(attn_mma,    cudaFuncAttributeMaxDynamicSharedMemorySize, ATTN_DYN);

    {
        int64_t tot = (int64_t)Bsz * Ssz * Dsz;
        embed_kernel<<<(unsigned)((tot + 255) / 256), 256>>>(tok, emb, x);
    }

    wsplit_kernel<<<dim3(Dsz/32, Dsz/32, NBlk), 256>>>(Wo, woth, wotl, Dsz, Dsz);
    wsplit_kernel<<<dim3(FFd/32, Dsz/32, NBlk), 256>>>(W1, w1th, w1tl, Dsz, FFd);
    wsplit_kernel<<<dim3(Dsz/32, FFd/32, NBlk), 256>>>(W2, w2th, w2tl, FFd, Dsz);

    const dim3 gemm_proj(1, MROWS / BM);
    const dim3 attn_grid(Ssz / 128, Bsz);
    const dim3 tc_wo(Dsz / GBN,  MROWS / GBM);
    const dim3 tc_f1(FFd / GBN,  MROWS / GBM);
    const dim3 tc_f2(Dsz / GBN,  MROWS / GBM);

    for (int l = 0; l < NBlk; ++l) {
        // head 0: D -> 96 (SIMT, bf16 hi/lo out)
        sgemm_kernel<3><<<gemm_proj, 256>>>(x, Dsz,
            W0 + (size_t)l * Dsz * QKVW, QKVW, b0 + (size_t)l * QKVW,
            nullptr, QKVW, qkvh, qkvl, Dsz);
        attn_mma<<<attn_grid, 128, ATTN_DYN>>>(qkvh, qkvl, xh, xhh, xhl);

        // chained heads 1..15: DH -> 96
        for (int h = 1; h < Hh; ++h) {
            const float* Whl = Wh + ((size_t)l * (Hh - 1) + (h - 1)) * DHd * QKVW;
            const float* bhl = bh + ((size_t)l * (Hh - 1) + (h - 1)) * QKVW;
            sgemm_kernel<3><<<gemm_proj, 256>>>(xh + (size_t)(h - 1) * DHd, Dsz,
                Whl, QKVW, bhl, nullptr, QKVW, qkvh, qkvl, DHd);
            attn_mma<<<attn_grid, 128, ATTN_DYN>>>(qkvh, qkvl,
                xh + (size_t)h * DHd, xhh + (size_t)h * DHd, xhl + (size_t)h * DHd);
        }

        // output projection + residual (mma), then LN1 (emit bf16)
        gemm_mma<0><<<tc_wo, 256, GDYN>>>(xhh, xhl,
            woth + (size_t)l * Dsz * Dsz, wotl + (size_t)l * Dsz * Dsz,
            bo + (size_t)l * Dsz, x, y, nullptr, nullptr, Dsz, Dsz);
        ln_kernel<true><<<MROWS, 128>>>(y, g1 + (size_t)l * Dsz, be1 + (size_t)l * Dsz,
                                        x, xbh, xbl);

        // FFN1 (mma, relu -> bf16 split)
        gemm_mma<1><<<tc_f1, 256, GDYN>>>(xbh, xbl,
            w1th + (size_t)l * FFd * Dsz, w1tl + (size_t)l * FFd * Dsz,
            b1 + (size_t)l * FFd, nullptr, nullptr, h1h, h1l, Dsz, FFd);

        // FFN2 (mma) + residual, then LN2
        gemm_mma<0><<<tc_f2, 256, GDYN>>>(h1h, h1l,
            w2th + (size_t)l * Dsz * FFd, w2tl + (size_t)l * Dsz * FFd,
            b2 + (size_t)l * Dsz, x, y, nullptr, nullptr, FFd, Dsz);
        ln_kernel<false><<<MROWS, 128>>>(y, g2 + (size_t)l * Dsz, be2 + (size_t)l * Dsz,
                                         x, nullptr, nullptr);
    }

    final_kernel<<<Bsz, 256>>>(x, Wf, bf_, out, out_size);
}

// round 9
// speedup vs baseline: 3.2558x; 1.1445x over previous
#include <cuda_runtime.h>
#include <cuda_bf16.h>
#include <math.h>
#include <stdint.h>

// Problem dims
#define Bsz   32
#define Ssz   1024
#define Dsz   512
#define Hh    16
#define NBlk  12
#define DHd   32
#define FFd   2048
#define MROWS (Bsz*Ssz)            // 32768
#define QKVW  96                   // 3*DHd

typedef __nv_bfloat16 bf16;

// ---------------- scratch (allocation-free: __device__ globals) ----------------
__device__ float g_x  [(size_t)MROWS*Dsz];    // current activations (fp32, resid)
__device__ float g_y  [(size_t)MROWS*Dsz];    // pre-LN temp
__device__ bf16  g_qkvh[(size_t)MROWS*QKVW];  // per-head q|k|v bf16 hi
__device__ bf16  g_qkvl[(size_t)MROWS*QKVW];  // per-head q|k|v bf16 lo
__device__ bf16  g_xhh[(size_t)MROWS*Dsz];    // concat head outs bf16 hi
__device__ bf16  g_xhl[(size_t)MROWS*Dsz];    // concat head outs bf16 lo
__device__ bf16  g_xbh[(size_t)MROWS*Dsz];    // post-LN1 bf16 hi
__device__ bf16  g_xbl[(size_t)MROWS*Dsz];    // post-LN1 bf16 lo
__device__ bf16  g_xch[(size_t)MROWS*Dsz];    // post-LN2 / embed bf16 hi
__device__ bf16  g_xcl[(size_t)MROWS*Dsz];    // post-LN2 / embed bf16 lo
__device__ bf16  g_h1h[(size_t)MROWS*FFd];    // ffn hidden bf16 hi
__device__ bf16  g_h1l[(size_t)MROWS*FFd];    // ffn hidden bf16 lo
__device__ bf16  g_woth[(size_t)NBlk*Dsz*Dsz];   // Wo^T  [N=512,K=512]
__device__ bf16  g_wotl[(size_t)NBlk*Dsz*Dsz];
__device__ bf16  g_w1th[(size_t)NBlk*FFd*Dsz];   // W1^T  [N=2048,K=512]
__device__ bf16  g_w1tl[(size_t)NBlk*FFd*Dsz];
__device__ bf16  g_w2th[(size_t)NBlk*Dsz*FFd];   // W2^T  [N=512,K=2048]
__device__ bf16  g_w2tl[(size_t)NBlk*Dsz*FFd];
__device__ bf16  g_w0th[(size_t)NBlk*QKVW*Dsz];  // W0^T  [96,512]
__device__ bf16  g_w0tl[(size_t)NBlk*QKVW*Dsz];
__device__ bf16  g_whth[(size_t)NBlk*(Hh-1)*QKVW*DHd];   // Wh^T [96,32] per (l,h)
__device__ bf16  g_whtl[(size_t)NBlk*(Hh-1)*QKVW*DHd];

// ================= low-level helpers =================
__device__ __forceinline__ uint32_t smem_u32(const void* p) {
    uint32_t a;
    asm("{ .reg .u64 t; cvta.to.shared.u64 t, %1; cvt.u32.u64 %0, t; }" : "=r"(a) : "l"(p));
    return a;
}
static __device__ __forceinline__ uint32_t swz128(uint32_t off) { return off ^ ((off >> 3) & 0x70u); }

__device__ __forceinline__ void cp16(uint32_t smem, const void* gmem) {
    asm volatile("cp.async.cg.shared.global [%0], [%1], 16;" :: "r"(smem), "l"(gmem));
}
__device__ __forceinline__ void cp_commit() { asm volatile("cp.async.commit_group;"); }
__device__ __forceinline__ void cp_wait0() { asm volatile("cp.async.wait_group 0;"); }
__device__ __forceinline__ void cp_wait1() { asm volatile("cp.async.wait_group 1;"); }

__device__ __forceinline__ void ldm_x4(uint32_t addr, uint32_t& r0, uint32_t& r1, uint32_t& r2, uint32_t& r3) {
    asm volatile("ldmatrix.sync.aligned.m8n8.x4.shared.b16 {%0,%1,%2,%3}, [%4];"
                 : "=r"(r0), "=r"(r1), "=r"(r2), "=r"(r3) : "r"(addr));
}
__device__ __forceinline__ void ldm_x4t(uint32_t addr, uint32_t& r0, uint32_t& r1, uint32_t& r2, uint32_t& r3) {
    asm volatile("ldmatrix.sync.aligned.m8n8.x4.trans.shared.b16 {%0,%1,%2,%3}, [%4];"
                 : "=r"(r0), "=r"(r1), "=r"(r2), "=r"(r3) : "r"(addr));
}
__device__ __forceinline__ void mma16816(float* c, uint32_t a0, uint32_t a1, uint32_t a2, uint32_t a3,
                                         uint32_t b0, uint32_t b1) {
    asm volatile("mma.sync.aligned.m16n8k16.row.col.f32.bf16.bf16.f32 "
                 "{%0,%1,%2,%3}, {%4,%5,%6,%7}, {%8,%9}, {%0,%1,%2,%3};"
                 : "+f"(c[0]), "+f"(c[1]), "+f"(c[2]), "+f"(c[3])
                 : "r"(a0), "r"(a1), "r"(a2), "r"(a3), "r"(b0), "r"(b1));
}
__device__ __forceinline__ unsigned pack_hi(float a, float b) {
    bf16 h0 = __float2bfloat16(a), h1 = __float2bfloat16(b);
    return (unsigned)__bfloat16_as_ushort(h0) | ((unsigned)__bfloat16_as_ushort(h1) << 16);
}
__device__ __forceinline__ unsigned pack_lo(float a, float b) {
    bf16 h0 = __float2bfloat16(a), h1 = __float2bfloat16(b);
    bf16 l0 = __float2bfloat16(a - __bfloat162float(h0));
    bf16 l1 = __float2bfloat16(b - __bfloat162float(h1));
    return (unsigned)__bfloat16_as_ushort(l0) | ((unsigned)__bfloat16_as_ushort(l1) << 16);
}

// ================= embedding + positional encoding (fp32 + hi/lo) =================
__global__ void embed_kernel(const int* __restrict__ tok,
                             const float* __restrict__ emb,
                             float* __restrict__ x,
                             bf16* __restrict__ xh, bf16* __restrict__ xl)
{
    int64_t i2 = ((int64_t)blockIdx.x * blockDim.x + threadIdx.x) * 2;
    if (i2 >= (int64_t)Bsz * Ssz * Dsz) return;
    float vv[2];
    #pragma unroll
    for (int u = 0; u < 2; ++u) {
        int64_t i = i2 + u;
        int d      = (int)(i & (Dsz - 1));
        int64_t bs = i >> 9;
        int s      = (int)(bs & (Ssz - 1));
        int t      = tok[bs];
        int j      = d >> 1;
        float e    = (2.0f * (float)j) / (float)Dsz;
        float freq = expf(-e * 9.210340371976184f);
        float ang  = (float)s * freq;
        float p    = (d & 1) ? cosf(ang) : sinf(ang);
        vv[u] = emb[(int64_t)t * Dsz + d] + p;
        x[i] = vv[u];
    }
    *(unsigned*)(xh + i2) = pack_hi(vv[0], vv[1]);
    *(unsigned*)(xl + i2) = pack_lo(vv[0], vv[1]);
}

// ================= weight transpose + bf16 split =================
// W [K,N] fp32 -> Th/Tl [N,K] bf16 (per z slab)
__global__ __launch_bounds__(256)
void wsplit_kernel(const float* __restrict__ W, bf16* __restrict__ Th, bf16* __restrict__ Tl,
                   int K, int N)
{
    __shared__ float t[32][33];
    int z = blockIdx.z;
    const float* Wz = W + (size_t)z * K * N;
    bf16* Thz = Th + (size_t)z * K * N;
    bf16* Tlz = Tl + (size_t)z * K * N;
    int n0 = blockIdx.x * 32, k0 = blockIdx.y * 32;
    int tx = threadIdx.x & 31, ty = threadIdx.x >> 5;
    #pragma unroll
    for (int i = 0; i < 4; ++i)
        t[ty + i*8][tx] = Wz[(size_t)(k0 + ty + i*8) * N + n0 + tx];
    __syncthreads();
    #pragma unroll
    for (int i = 0; i < 4; ++i) {
        float v = t[tx][ty + i*8];
        bf16 h = __float2bfloat16(v);
        bf16 lo = __float2bfloat16(v - __bfloat162float(h));
        size_t o = (size_t)(n0 + ty + i*8) * K + k0 + tx;
        Thz[o] = h; Tlz[o] = lo;
    }
}

// ================= mma.sync bf16-split GEMM (big GEMMs), 128x64 tile, 2 CTAs/SM =================
#define GBM 128
#define GBN 64
#define GBK 64
#define ST_AH 0
#define ST_AL 16384
#define ST_BH 32768
#define ST_BL 40960
#define STAGE_BYTES 49152
#define GDYN (2*STAGE_BYTES)

template<int EPI>
__global__ __launch_bounds__(256, 2)
void gemm_mma(const bf16* __restrict__ Ah, const bf16* __restrict__ Al,
              const bf16* __restrict__ Bh, const bf16* __restrict__ Bl,
              const float* __restrict__ bias,
              const float* __restrict__ resid,
              float* __restrict__ Cf,
              bf16* __restrict__ Chh, bf16* __restrict__ Chl,
              int K, int Nld)
{
    extern __shared__ char dsm[];
    const uint32_t sb = smem_u32(dsm);

    const int tid  = threadIdx.x;
    const int lane = tid & 31;
    const int w    = tid >> 5;           // 8 warps
    const int wm   = w >> 1;             // 0..3 (32-row slice)
    const int wn   = w & 1;              // 0..1 (32-col slice)
    const int row0 = blockIdx.y * GBM;
    const int col0 = blockIdx.x * GBN;

    float acc[2][4][4];
    #pragma unroll
    for (int i = 0; i < 2; ++i)
        #pragma unroll
        for (int j = 0; j < 4; ++j)
            #pragma unroll
            for (int k = 0; k < 4; ++k) acc[i][j][k] = 0.f;

    const int nchunks = K / GBK;

    auto load_stage = [&](int c, int st) {
        const uint32_t s0 = sb + st * STAGE_BYTES;
        const size_t kofs = (size_t)c * GBK;
        const int lr = tid >> 3, lc = tid & 7;
        #pragma unroll
        for (int i = 0; i < 4; ++i) {
            int r = lr + i * 32;
            uint32_t so = swz128((uint32_t)(r * 128 + lc * 16));
            size_t g = (size_t)(row0 + r) * K + kofs + lc * 8;
            cp16(s0 + ST_AH + so, Ah + g);
            cp16(s0 + ST_AL + so, Al + g);
        }
        #pragma unroll
        for (int i = 0; i < 2; ++i) {
            int r = lr + i * 32;
            uint32_t so = swz128((uint32_t)(r * 128 + lc * 16));
            size_t g = (size_t)(col0 + r) * K + kofs + lc * 8;
            cp16(s0 + ST_BH + so, Bh + g);
            cp16(s0 + ST_BL + so, Bl + g);
        }
        cp_commit();
    };

    load_stage(0, 0);

    for (int c = 0; c < nchunks; ++c) {
        const int st = c & 1;
        if (c + 1 < nchunks) { load_stage(c + 1, st ^ 1); cp_wait1(); }
        else                 { cp_wait0(); }
        __syncthreads();

        const uint32_t s0 = sb + st * STAGE_BYTES;
        const int arow  = wm * 32 + (lane & 15);
        const int acolb = (lane >> 4) << 4;
        const int bcolb = ((lane >> 3) & 1) << 4;

        #pragma unroll
        for (int slab = 0; slab < 4; ++slab) {
            const int kb = slab * 32;
            uint32_t ah[2][4], al[2][4], bh[2][4], bl[2][4];
            #pragma unroll
            for (int mf = 0; mf < 2; ++mf) {
                uint32_t ao = swz128((uint32_t)((arow + mf*16) * 128 + kb + acolb));
                ldm_x4(s0 + ST_AH + ao, ah[mf][0], ah[mf][1], ah[mf][2], ah[mf][3]);
                ldm_x4(s0 + ST_AL + ao, al[mf][0], al[mf][1], al[mf][2], al[mf][3]);
            }
            #pragma unroll
            for (int ng = 0; ng < 2; ++ng) {
                int nrow = wn * 32 + ng * 16 + ((lane >> 4) << 3) + (lane & 7);
                uint32_t bo = swz128((uint32_t)(nrow * 128 + kb + bcolb));
                ldm_x4(s0 + ST_BH + bo, bh[ng][0], bh[ng][1], bh[ng][2], bh[ng][3]);
                ldm_x4(s0 + ST_BL + bo, bl[ng][0], bl[ng][1], bl[ng][2], bl[ng][3]);
            }
            #pragma unroll
            for (int mf = 0; mf < 2; ++mf) {
                #pragma unroll
                for (int ng = 0; ng < 2; ++ng) {
                    mma16816(acc[mf][2*ng],   ah[mf][0], ah[mf][1], ah[mf][2], ah[mf][3], bh[ng][0], bh[ng][1]);
                    mma16816(acc[mf][2*ng+1], ah[mf][0], ah[mf][1], ah[mf][2], ah[mf][3], bh[ng][2], bh[ng][3]);
                    mma16816(acc[mf][2*ng],   ah[mf][0], ah[mf][1], ah[mf][2], ah[mf][3], bl[ng][0], bl[ng][1]);
                    mma16816(acc[mf][2*ng+1], ah[mf][0], ah[mf][1], ah[mf][2], ah[mf][3], bl[ng][2], bl[ng][3]);
                    mma16816(acc[mf][2*ng],   al[mf][0], al[mf][1], al[mf][2], al[mf][3], bh[ng][0], bh[ng][1]);
                    mma16816(acc[mf][2*ng+1], al[mf][0], al[mf][1], al[mf][2], al[mf][3], bh[ng][2], bh[ng][3]);
                }
            }
        }
        __syncthreads();
    }

    const int rg = lane >> 2;
    const int cg = (lane & 3) * 2;
    #pragma unroll
    for (int mf = 0; mf < 2; ++mf) {
        const int rbase = row0 + wm*32 + mf*16 + rg;
        #pragma unroll
        for (int nf = 0; nf < 4; ++nf) {
            const int col = col0 + wn*32 + nf*8 + cg;
            const float2 bia = *(const float2*)(bias + col);
            float f0 = acc[mf][nf][0] + bia.x;
            float f1 = acc[mf][nf][1] + bia.y;
            float f2 = acc[mf][nf][2] + bia.x;
            float f3 = acc[mf][nf][3] + bia.y;
            if (EPI == 0) {
                const float2 r0v = *(const float2*)(resid + (size_t)rbase * Nld + col);
                const float2 r1v = *(const float2*)(resid + (size_t)(rbase+8) * Nld + col);
                *(float2*)(Cf + (size_t)rbase * Nld + col)     = make_float2(f0 + r0v.x, f1 + r0v.y);
                *(float2*)(Cf + (size_t)(rbase+8) * Nld + col) = make_float2(f2 + r1v.x, f3 + r1v.y);
            } else {
                f0 = fmaxf(f0, 0.f); f1 = fmaxf(f1, 0.f);
                f2 = fmaxf(f2, 0.f); f3 = fmaxf(f3, 0.f);
                *(unsigned*)(Chh + (size_t)rbase * Nld + col)     = pack_hi(f0, f1);
                *(unsigned*)(Chh + (size_t)(rbase+8) * Nld + col) = pack_hi(f2, f3);
                *(unsigned*)(Chl + (size_t)rbase * Nld + col)     = pack_lo(f0, f1);
                *(unsigned*)(Chl + (size_t)(rbase+8) * Nld + col) = pack_lo(f2, f3);
            }
        }
    }
}

// ================= mma projection: C[M,96] = A[M,K] @ Wt[96,K]^T + bias -> hi/lo =================
// 80B-padded rows (attention pattern, conflict-free ldmatrix, no swizzle)
#define PTRS 80
#define P_AH 0
#define P_AL 10240
#define P_BH 20480
#define P_BL 28160
#define P_STG 35840
#define P_DYN (2*P_STG)

__global__ __launch_bounds__(128)
void proj_mma(const bf16* __restrict__ Ah, const bf16* __restrict__ Al, int lda,
              const bf16* __restrict__ Wth, const bf16* __restrict__ Wtl,
              const float* __restrict__ bias,
              bf16* __restrict__ Chh, bf16* __restrict__ Chl, int K)
{
    extern __shared__ char psm[];
    const uint32_t sb = smem_u32(psm);
    const int tid = threadIdx.x, lane = tid & 31, w = tid >> 5;
    const int row0 = blockIdx.x * 128;
    const int nch = K / 32;

    auto load = [&](int c, int st) {
        const uint32_t s0 = sb + st * P_STG;
        const int k0 = c * 32;
        #pragma unroll
        for (int i = 0; i < 4; ++i) {
            int idx = tid + i * 128;
            int r = idx >> 2, cc = idx & 3;
            size_t g = (size_t)(row0 + r) * lda + k0 + cc * 8;
            cp16(s0 + P_AH + r * PTRS + cc * 16, Ah + g);
            cp16(s0 + P_AL + r * PTRS + cc * 16, Al + g);
        }
        #pragma unroll
        for (int i = 0; i < 3; ++i) {
            int idx = tid + i * 128;
            int r = idx >> 2, cc = idx & 3;
            size_t g = (size_t)r * K + k0 + cc * 8;
            cp16(s0 + P_BH + r * PTRS + cc * 16, Wth + g);
            cp16(s0 + P_BL + r * PTRS + cc * 16, Wtl + g);
        }
        cp_commit();
    };

    float acc[2][12][4];
    #pragma unroll
    for (int i = 0; i < 2; ++i)
        #pragma unroll
        for (int j = 0; j < 12; ++j)
            #pragma unroll
            for (int k = 0; k < 4; ++k) acc[i][j][k] = 0.f;

    load(0, 0);
    for (int c = 0; c < nch; ++c) {
        const int st = c & 1;
        if (c + 1 < nch) { load(c + 1, st ^ 1); cp_wait1(); }
        else             { cp_wait0(); }
        __syncthreads();
        const uint32_t s0 = sb + st * P_STG;

        #pragma unroll
        for (int ks = 0; ks < 2; ++ks) {
            uint32_t ahf[2][4], alf[2][4];
            #pragma unroll
            for (int mf = 0; mf < 2; ++mf) {
                uint32_t ad = s0 + (uint32_t)((w*32 + mf*16 + (lane & 15)) * PTRS + ks*32 + ((lane >> 4) << 4));
                ldm_x4(ad + P_AH, ahf[mf][0], ahf[mf][1], ahf[mf][2], ahf[mf][3]);
                ldm_x4(ad + P_AL, alf[mf][0], alf[mf][1], alf[mf][2], alf[mf][3]);
            }
            #pragma unroll
            for (int ng = 0; ng < 6; ++ng) {
                uint32_t bhf[4], blf[4];
                uint32_t bd = s0 + (uint32_t)((ng*16 + ((lane >> 4) << 3) + (lane & 7)) * PTRS
                                              + ks*32 + (((lane >> 3) & 1) << 4));
                ldm_x4(bd + P_BH, bhf[0], bhf[1], bhf[2], bhf[3]);
                ldm_x4(bd + P_BL, blf[0], blf[1], blf[2], blf[3]);
                #pragma unroll
                for (int mf = 0; mf < 2; ++mf) {
                    mma16816(acc[mf][2*ng],   ahf[mf][0], ahf[mf][1], ahf[mf][2], ahf[mf][3], bhf[0], bhf[1]);
                    mma16816(acc[mf][2*ng+1], ahf[mf][0], ahf[mf][1], ahf[mf][2], ahf[mf][3], bhf[2], bhf[3]);
                    mma16816(acc[mf][2*ng],   ahf[mf][0], ahf[mf][1], ahf[mf][2], ahf[mf][3], blf[0], blf[1]);
                    mma16816(acc[mf][2*ng+1], ahf[mf][0], ahf[mf][1], ahf[mf][2], ahf[mf][3], blf[2], blf[3]);
                    mma16816(acc[mf][2*ng],   alf[mf][0], alf[mf][1], alf[mf][2], alf[mf][3], bhf[0], bhf[1]);
                    mma16816(acc[mf][2*ng+1], alf[mf][0], alf[mf][1], alf[mf][2], alf[mf][3], bhf[2], bhf[3]);
                }
            }
        }
        __syncthreads();
    }

    const int rg = lane >> 2, cg = (lane & 3) * 2;
    #pragma unroll
    for (int mf = 0; mf < 2; ++mf) {
        const int r0 = row0 + w*32 + mf*16 + rg;
        #pragma unroll
        for (int nf = 0; nf < 12; ++nf) {
            const int col = nf * 8 + cg;
            const float2 bia = *(const float2*)(bias + col);
            float f0 = acc[mf][nf][0] + bia.x;
            float f1 = acc[mf][nf][1] + bia.y;
            float f2 = acc[mf][nf][2] + bia.x;
            float f3 = acc[mf][nf][3] + bia.y;
            *(unsigned*)(Chh + (size_t)r0 * QKVW + col)       = pack_hi(f0, f1);
            *(unsigned*)(Chh + (size_t)(r0+8) * QKVW + col)   = pack_hi(f2, f3);
            *(unsigned*)(Chl + (size_t)r0 * QKVW + col)       = pack_lo(f0, f1);
            *(unsigned*)(Chl + (size_t)(r0+8) * QKVW + col)   = pack_lo(f2, f3);
        }
    }
}

// ================= mma.sync flash attention (single-pass, scores tiny) =================
#define ATTN_SCALE 0.03125f   // 1/sqrt(1024)
#define ATRS 80
#define AQH 0
#define AQL 10240
#define AKV0 20480
#define AKVSTG 20480
#define AOKH 0
#define AOKL 5120
#define AOVH 10240
#define AOVL 15360
#define ATTN_DYN 61440

__global__ __launch_bounds__(128)
void attn_mma(const bf16* __restrict__ qkvh, const bf16* __restrict__ qkvl,
              bf16* __restrict__ outh, bf16* __restrict__ outl)
{
    extern __shared__ char asmem[];
    const uint32_t sb = smem_u32(asmem);
    const int tid = threadIdx.x, lane = tid & 31, w = tid >> 5;
    const int b = blockIdx.y;
    const int q0 = blockIdx.x * 128;
    const size_t base = (size_t)b * Ssz * QKVW;

    #pragma unroll
    for (int i = 0; i < 4; ++i) {
        int idx = tid + i * 128;
        int r = idx >> 2, c = idx & 3;
        size_t g = base + (size_t)(q0 + r) * QKVW + c * 8;
        cp16(sb + AQH + r * ATRS + c * 16, qkvh + g);
        cp16(sb + AQL + r * ATRS + c * 16, qkvl + g);
    }
    cp_commit();
    {
        const uint32_t s0 = sb + AKV0;
        #pragma unroll
        for (int i = 0; i < 2; ++i) {
            int idx = tid + i * 128;
            int r = idx >> 2, c = idx & 3;
            size_t gk = base + (size_t)r * QKVW + 32 + c * 8;
            cp16(s0 + AOKH + r * ATRS + c * 16, qkvh + gk);
            cp16(s0 + AOKL + r * ATRS + c * 16, qkvl + gk);
            cp16(s0 + AOVH + r * ATRS + c * 16, qkvh + gk + 32);
            cp16(s0 + AOVL + r * ATRS + c * 16, qkvl + gk + 32);
        }
        cp_commit();
    }
    cp_wait1();
    __syncthreads();

    uint32_t qh[2][2][4], ql[2][2][4];
    #pragma unroll
    for (int mf = 0; mf < 2; ++mf)
        #pragma unroll
        for (int ks = 0; ks < 2; ++ks) {
            uint32_t ad = sb + (uint32_t)((w * 32 + mf * 16 + (lane & 15)) * ATRS + ks * 32 + ((lane >> 4) << 4));
            ldm_x4(ad + AQH, qh[mf][ks][0], qh[mf][ks][1], qh[mf][ks][2], qh[mf][ks][3]);
            ldm_x4(ad + AQL, ql[mf][ks][0], ql[mf][ks][1], ql[mf][ks][2], ql[mf][ks][3]);
        }

    float o[2][4][4];
    float lsum[2][2];
    #pragma unroll
    for (int mf = 0; mf < 2; ++mf) {
        lsum[mf][0] = 0.f; lsum[mf][1] = 0.f;
        #pragma unroll
        for (int n8 = 0; n8 < 4; ++n8)
            #pragma unroll
            for (int j = 0; j < 4; ++j) o[mf][n8][j] = 0.f;
    }

    for (int c = 0; c < 16; ++c) {
        const int st = c & 1;
        if (c < 15) {
            const uint32_t s1 = sb + AKV0 + (st ^ 1) * AKVSTG;
            #pragma unroll
            for (int i = 0; i < 2; ++i) {
                int idx = tid + i * 128;
                int r = idx >> 2, cc = idx & 3;
                size_t gk = base + (size_t)((c + 1) * 64 + r) * QKVW + 32 + cc * 8;
                cp16(s1 + AOKH + r * ATRS + cc * 16, qkvh + gk);
                cp16(s1 + AOKL + r * ATRS + cc * 16, qkvl + gk);
                cp16(s1 + AOVH + r * ATRS + cc * 16, qkvh + gk + 32);
                cp16(s1 + AOVL + r * ATRS + cc * 16, qkvl + gk + 32);
            }
            cp_commit(); cp_wait1();
        } else cp_wait0();
        __syncthreads();

        const uint32_t kb = sb + AKV0 + st * AKVSTG;

        #pragma unroll
        for (int g = 0; g < 4; ++g) {
            float s[2][2][4];
            #pragma unroll
            for (int mf = 0; mf < 2; ++mf)
                #pragma unroll
                for (int f = 0; f < 2; ++f)
                    #pragma unroll
                    for (int j = 0; j < 4; ++j) s[mf][f][j] = 0.f;

            #pragma unroll
            for (int ks = 0; ks < 2; ++ks) {
                uint32_t kh[4], kl[4];
                uint32_t ad = kb + (uint32_t)((g * 16 + ((lane >> 4) << 3) + (lane & 7)) * ATRS
                                              + ks * 32 + (((lane >> 3) & 1) << 4));
                ldm_x4(ad + AOKH, kh[0], kh[1], kh[2], kh[3]);
                ldm_x4(ad + AOKL, kl[0], kl[1], kl[2], kl[3]);
                #pragma unroll
                for (int mf = 0; mf < 2; ++mf) {
                    mma16816(s[mf][0], qh[mf][ks][0], qh[mf][ks][1], qh[mf][ks][2], qh[mf][ks][3], kh[0], kh[1]);
                    mma16816(s[mf][1], qh[mf][ks][0], qh[mf][ks][1], qh[mf][ks][2], qh[mf][ks][3], kh[2], kh[3]);
                    mma16816(s[mf][0], qh[mf][ks][0], qh[mf][ks][1], qh[mf][ks][2], qh[mf][ks][3], kl[0], kl[1]);
                    mma16816(s[mf][1], qh[mf][ks][0], qh[mf][ks][1], qh[mf][ks][2], qh[mf][ks][3], kl[2], kl[3]);
                    mma16816(s[mf][0], ql[mf][ks][0], ql[mf][ks][1], ql[mf][ks][2], ql[mf][ks][3], kh[0], kh[1]);
                    mma16816(s[mf][1], ql[mf][ks][0], ql[mf][ks][1], ql[mf][ks][2], ql[mf][ks][3], kh[2], kh[3]);
                }
            }

            uint32_t ph[2][4], pl[2][4];
            #pragma unroll
            for (int mf = 0; mf < 2; ++mf) {
                float p[2][4];
                #pragma unroll
                for (int f = 0; f < 2; ++f)
                    #pragma unroll
                    for (int j = 0; j < 4; ++j)
                        p[f][j] = __expf(s[mf][f][j] * ATTN_SCALE);
                lsum[mf][0] += p[0][0] + p[0][1] + p[1][0] + p[1][1];
                lsum[mf][1] += p[0][2] + p[0][3] + p[1][2] + p[1][3];
                #pragma unroll
                for (int f = 0; f < 2; ++f) {
                    ph[mf][2*f]   = pack_hi(p[f][0], p[f][1]);
                    ph[mf][2*f+1] = pack_hi(p[f][2], p[f][3]);
                    pl[mf][2*f]   = pack_lo(p[f][0], p[f][1]);
                    pl[mf][2*f+1] = pack_lo(p[f][2], p[f][3]);
                }
            }

            uint32_t vh[2][4], vl[2][4];
            #pragma unroll
            for (int nw = 0; nw < 2; ++nw) {
                uint32_t ad = kb + (uint32_t)((g * 16 + ((lane >> 3) & 1) * 8 + (lane & 7)) * ATRS
                                              + nw * 32 + ((lane >> 4) << 4));
                ldm_x4t(ad + AOVH, vh[nw][0], vh[nw][1], vh[nw][2], vh[nw][3]);
                ldm_x4t(ad + AOVL, vl[nw][0], vl[nw][1], vl[nw][2], vl[nw][3]);
            }
            #pragma unroll
            for (int mf = 0; mf < 2; ++mf)
                #pragma unroll
                for (int n8 = 0; n8 < 4; ++n8) {
                    const int nw = n8 >> 1, pr = (n8 & 1) * 2;
                    mma16816(o[mf][n8], ph[mf][0], ph[mf][1], ph[mf][2], ph[mf][3], vh[nw][pr], vh[nw][pr+1]);
                    mma16816(o[mf][n8], ph[mf][0], ph[mf][1], ph[mf][2], ph[mf][3], vl[nw][pr], vl[nw][pr+1]);
                    mma16816(o[mf][n8], pl[mf][0], pl[mf][1], pl[mf][2], pl[mf][3], vh[nw][pr], vh[nw][pr+1]);
                }
        }
        __syncthreads();
    }

    #pragma unroll
    for (int mf = 0; mf < 2; ++mf)
        #pragma unroll
        for (int hh = 0; hh < 2; ++hh) {
            float v = lsum[mf][hh];
            v += __shfl_xor_sync(0xffffffffu, v, 1);
            v += __shfl_xor_sync(0xffffffffu, v, 2);
            lsum[mf][hh] = 1.f / v;
        }
    const int rg = lane >> 2, cg = (lane & 3) * 2;
    #pragma unroll
    for (int mf = 0; mf < 2; ++mf) {
        const int r0 = q0 + w * 32 + mf * 16 + rg;
        #pragma unroll
        for (int n8 = 0; n8 < 4; ++n8) {
            const int col = n8 * 8 + cg;
            float f0 = o[mf][n8][0] * lsum[mf][0];
            float f1 = o[mf][n8][1] * lsum[mf][0];
            float f2 = o[mf][n8][2] * lsum[mf][1];
            float f3 = o[mf][n8][3] * lsum[mf][1];
            size_t off0 = ((size_t)b * Ssz + r0) * Dsz + col;
            size_t off1 = off0 + (size_t)8 * Dsz;
            *(unsigned*)(outh + off0) = pack_hi(f0, f1);
            *(unsigned*)(outh + off1) = pack_hi(f2, f3);
            *(unsigned*)(outl + off0) = pack_lo(f0, f1);
            *(unsigned*)(outl + off1) = pack_lo(f2, f3);
        }
    }
}

// ================= LayerNorm (512, eps=1e-3) + bf16 split emit =================
__global__ __launch_bounds__(128)
void ln_kernel(const float* __restrict__ y, const float* __restrict__ g,
               const float* __restrict__ be, float* __restrict__ x,
               bf16* __restrict__ xh, bf16* __restrict__ xl)
{
    const int row = blockIdx.x;
    const int t = threadIdx.x;
    const float* yr = y + (size_t)row * Dsz;
    float4 v = *(const float4*)(yr + t * 4);
    float sum = v.x + v.y + v.z + v.w;
    float sq  = v.x*v.x + v.y*v.y + v.z*v.z + v.w*v.w;
    #pragma unroll
    for (int o = 16; o > 0; o >>= 1) {
        sum += __shfl_down_sync(0xffffffffu, sum, o);
        sq  += __shfl_down_sync(0xffffffffu, sq,  o);
    }
    __shared__ float ws[4], ws2[4];
    int warp = t >> 5, lane = t & 31;
    if (lane == 0) { ws[warp] = sum; ws2[warp] = sq; }
    __syncthreads();
    if (t == 0) {
        ws[0]  = ws[0] + ws[1] + ws[2] + ws[3];
        ws2[0] = ws2[0] + ws2[1] + ws2[2] + ws2[3];
    }
    __syncthreads();
    const float mean = ws[0] * (1.f / (float)Dsz);
    const float var  = ws2[0] * (1.f / (float)Dsz) - mean * mean;
    const float r    = rsqrtf(var + 1e-3f);
    float4 gg = *(const float4*)(g + t * 4);
    float4 bb = *(const float4*)(be + t * 4);
    float4 out;
    out.x = (v.x - mean) * r * gg.x + bb.x;
    out.y = (v.y - mean) * r * gg.y + bb.y;
    out.z = (v.z - mean) * r * gg.z + bb.z;
    out.w = (v.w - mean) * r * gg.w + bb.w;
    *(float4*)(x + (size_t)row * Dsz + t * 4) = out;
    uint2 uh, ul;
    uh.x = pack_hi(out.x, out.y); uh.y = pack_hi(out.z, out.w);
    ul.x = pack_lo(out.x, out.y); ul.y = pack_lo(out.z, out.w);
    *(uint2*)(xh + (size_t)row * Dsz + t * 4) = uh;
    *(uint2*)(xl + (size_t)row * Dsz + t * 4) = ul;
}

// ================= mean-pool + final dense + sigmoid =================
__global__ __launch_bounds__(256)
void final_kernel(const float* __restrict__ x, const float* __restrict__ Wf,
                  const float* __restrict__ bf_, float* __restrict__ out, int out_size)
{
    const int b = blockIdx.x;
    const float* xb = x + (size_t)b * Ssz * Dsz;
    float acc = 0.f;
    for (int i = threadIdx.x; i < (Ssz * Dsz) / 4; i += 256) {
        float4 v = *(const float4*)(xb + (size_t)i * 4);
        int d = (i * 4) & (Dsz - 1);
        acc += v.x * Wf[d] + v.y * Wf[d+1] + v.z * Wf[d+2] + v.w * Wf[d+3];
    }
    #pragma unroll
    for (int o = 16; o > 0; o >>= 1) acc += __shfl_down_sync(0xffffffffu, acc, o);
    __shared__ float ws[8];
    int warp = threadIdx.x >> 5, lane = threadIdx.x & 31;
    if (lane == 0) ws[warp] = acc;
    __syncthreads();
    if (threadIdx.x == 0) {
        float tot = 0.f;
        #pragma unroll
        for (int w = 0; w < 8; ++w) tot += ws[w];
        float logit = tot * (1.f / (float)Ssz) + bf_[0];
        if (b < out_size) out[b] = logit;
        if (Bsz + b < out_size) out[Bsz + b] = 1.f / (1.f + expf(-logit));
    }
}

// ================= orchestration =================
extern "C" void kernel_launch(void* const* d_in, const int* in_sizes, int n_in,
                              void* d_out, int out_size)
{
    const int*   tok = (const int*)  d_in[0];
    const float* emb = (const float*)d_in[1];
    const float* W0  = (const float*)d_in[2];
    const float* b0  = (const float*)d_in[3];
    const float* Wh  = (const float*)d_in[4];
    const float* bh  = (const float*)d_in[5];
    const float* Wo  = (const float*)d_in[6];
    const float* bo  = (const float*)d_in[7];
    const float* g1  = (const float*)d_in[8];
    const float* be1 = (const float*)d_in[9];
    const float* W1  = (const float*)d_in[10];
    const float* b1  = (const float*)d_in[11];
    const float* W2  = (const float*)d_in[12];
    const float* b2  = (const float*)d_in[13];
    const float* g2  = (const float*)d_in[14];
    const float* be2 = (const float*)d_in[15];
    const float* Wf  = (const float*)d_in[16];
    const float* bf_ = (const float*)d_in[17];
    float* out = (float*)d_out;

    float *x, *y;
    bf16 *qkvh, *qkvl, *xhh, *xhl, *xbh, *xbl, *xch, *xcl, *h1h, *h1l;
    bf16 *woth, *wotl, *w1th, *w1tl, *w2th, *w2tl, *w0th, *w0tl, *whth, *whtl;
    cudaGetSymbolAddress((void**)&x,    g_x);
    cudaGetSymbolAddress((void**)&y,    g_y);
    cudaGetSymbolAddress((void**)&qkvh, g_qkvh);
    cudaGetSymbolAddress((void**)&qkvl, g_qkvl);
    cudaGetSymbolAddress((void**)&xhh,  g_xhh);
    cudaGetSymbolAddress((void**)&xhl,  g_xhl);
    cudaGetSymbolAddress((void**)&xbh,  g_xbh);
    cudaGetSymbolAddress((void**)&xbl,  g_xbl);
    cudaGetSymbolAddress((void**)&xch,  g_xch);
    cudaGetSymbolAddress((void**)&xcl,  g_xcl);
    cudaGetSymbolAddress((void**)&h1h,  g_h1h);
    cudaGetSymbolAddress((void**)&h1l,  g_h1l);
    cudaGetSymbolAddress((void**)&woth, g_woth);
    cudaGetSymbolAddress((void**)&wotl, g_wotl);
    cudaGetSymbolAddress((void**)&w1th, g_w1th);
    cudaGetSymbolAddress((void**)&w1tl, g_w1tl);
    cudaGetSymbolAddress((void**)&w2th, g_w2th);
    cudaGetSymbolAddress((void**)&w2tl, g_w2tl);
    cudaGetSymbolAddress((void**)&w0th, g_w0th);
    cudaGetSymbolAddress((void**)&w0tl, g_w0tl);
    cudaGetSymbolAddress((void**)&whth, g_whth);
    cudaGetSymbolAddress((void**)&whtl, g_whtl);

    cudaFuncSetAttribute(gemm_mma<0>, cudaFuncAttributeMaxDynamicSharedMemorySize, GDYN);
    cudaFuncSetAttribute(gemm_mma<1>, cudaFuncAttributeMaxDynamicSharedMemorySize, GDYN);
    cudaFuncSetAttribute(attn_mma,    cudaFuncAttributeMaxDynamicSharedMemorySize, ATTN_DYN);
    cudaFuncSetAttribute(proj_mma,    cudaFuncAttributeMaxDynamicSharedMemorySize, P_DYN);

    {
        int64_t tot = (int64_t)Bsz * Ssz * Dsz / 2;
        embed_kernel<<<(unsigned)((tot + 255) / 256), 256>>>(tok, emb, x, xch, xcl);
    }

    // weight transpose + bf16 split
    wsplit_kernel<<<dim3(Dsz/32, Dsz/32, NBlk), 256>>>(Wo, woth, wotl, Dsz, Dsz);
    wsplit_kernel<<<dim3(FFd/32, Dsz/32, NBlk), 256>>>(W1, w1th, w1tl, Dsz, FFd);
    wsplit_kernel<<<dim3(Dsz/32, FFd/32, NBlk), 256>>>(W2, w2th, w2tl, FFd, Dsz);
    wsplit_kernel<<<dim3(QKVW/32, Dsz/32, NBlk), 256>>>(W0, w0th, w0tl, Dsz, QKVW);
    wsplit_kernel<<<dim3(QKVW/32, 1, NBlk*(Hh-1)), 256>>>(Wh, whth, whtl, DHd, QKVW);

    const dim3 attn_grid(Ssz / 128, Bsz);
    const dim3 tc_wo(Dsz / GBN,  MROWS / GBM);   // (8, 256)
    const dim3 tc_f1(FFd / GBN,  MROWS / GBM);   // (32, 256)
    const dim3 tc_f2(Dsz / GBN,  MROWS / GBM);   // (8, 256)

    for (int l = 0; l < NBlk; ++l) {
        // head 0: D -> 96 (mma, reads post-LN2/embed hi/lo)
        proj_mma<<<MROWS/128, 128, P_DYN>>>(xch, xcl, Dsz,
            w0th + (size_t)l * QKVW * Dsz, w0tl + (size_t)l * QKVW * Dsz,
            b0 + (size_t)l * QKVW, qkvh, qkvl, Dsz);
        attn_mma<<<attn_grid, 128, ATTN_DYN>>>(qkvh, qkvl, xhh, xhl);

        // chained heads 1..15: DH -> 96
        for (int h = 1; h < Hh; ++h) {
            const size_t wo = ((size_t)l * (Hh - 1) + (h - 1)) * QKVW * DHd;
            proj_mma<<<MROWS/128, 128, P_DYN>>>(
                xhh + (size_t)(h - 1) * DHd, xhl + (size_t)(h - 1) * DHd, Dsz,
                whth + wo, whtl + wo,
                bh + ((size_t)l * (Hh - 1) + (h - 1)) * QKVW, qkvh, qkvl, DHd);
            attn_mma<<<attn_grid, 128, ATTN_DYN>>>(qkvh, qkvl,
                xhh + (size_t)h * DHd, xhl + (size_t)h * DHd);
        }

        // output projection + residual (mma), then LN1 (emit bf16)
        gemm_mma<0><<<tc_wo, 256, GDYN>>>(xhh, xhl,
            woth + (size_t)l * Dsz * Dsz, wotl + (size_t)l * Dsz * Dsz,
            bo + (size_t)l * Dsz, x, y, nullptr, nullptr, Dsz, Dsz);
        ln_kernel<<<MROWS, 128>>>(y, g1 + (size_t)l * Dsz, be1 + (size_t)l * Dsz,
                                  x, xbh, xbl);

        // FFN1 (mma, relu -> bf16 split)
        gemm_mma<1><<<tc_f1, 256, GDYN>>>(xbh, xbl,
            w1th + (size_t)l * FFd * Dsz, w1tl + (size_t)l * FFd * Dsz,
            b1 + (size_t)l * FFd, nullptr, nullptr, h1h, h1l, Dsz, FFd);

        // FFN2 (mma) + residual, then LN2 (emit bf16 for next layer head0)
        gemm_mma<0><<<tc_f2, 256, GDYN>>>(h1h, h1l,
            w2th + (size_t)l * Dsz * FFd, w2tl + (size_t)l * Dsz * FFd,
            b2 + (size_t)l * Dsz, x, y, nullptr, nullptr, FFd, Dsz);
        ln_kernel<<<MROWS, 128>>>(y, g2 + (size_t)l * Dsz, be2 + (size_t)l * Dsz,
                                  x, xch, xcl);
    }

    final_kernel<<<Bsz, 256>>>(x, Wf, bf_, out, out_size);
}